// round 8
// baseline (speedup 1.0000x reference)
#include <cuda_runtime.h>
#include <math.h>

// ---------------------------------------------------------------------------
// Problem constants
// ---------------------------------------------------------------------------
#define B_     8
#define N_     2048
#define M_     32768
#define QD_    512
#define DR_    256
#define D_     512
#define H_     8
#define DH_    64
#define INNER_ 512
#define TOPK_  8
#define SCALE_ 0.125f

#define DIST_BLOCKS 128
#define NCAND (DIST_BLOCKS * TOPK_)   // 1024

// ---------------------------------------------------------------------------
// Scratch
// ---------------------------------------------------------------------------
__device__ float g_e0[B_ * DR_];
__device__ float g_cand_d2[B_ * NCAND];
__device__ int   g_cand_idx[B_ * NCAND];
__device__ int   g_topk_idx[B_ * TOPK_];
__device__ float g_WqT[QD_ * INNER_];     // WqT[i][p] = Wq[p][i]
__device__ float g_kappa[B_ * QD_ * 64];  // [b][p][c], c=j*8+h (SCALE folded)
__device__ float g_vw[B_ * 64 * INNER_];  // [b][c][o]

// ---------------------------------------------------------------------------
// f32x2 helpers
// ---------------------------------------------------------------------------
__device__ __forceinline__ unsigned long long splat2(float f) {
    unsigned long long r;
    asm("mov.b64 %0, {%1, %1};" : "=l"(r) : "f"(f));
    return r;
}
__device__ __forceinline__ void fma2(unsigned long long& d,
                                     unsigned long long a,
                                     unsigned long long b) {
    asm("fma.rn.f32x2 %0, %1, %2, %0;" : "+l"(d) : "l"(a), "l"(b));
}
__device__ __forceinline__ float2 unpack2(unsigned long long v) {
    float2 r;
    asm("mov.b64 {%0, %1}, %2;" : "=f"(r.x), "=f"(r.y) : "l"(v));
    return r;
}

// ---------------------------------------------------------------------------
// Kernel 0: transpose Wq -> g_WqT
// ---------------------------------------------------------------------------
__global__ void transpose512(const float* __restrict__ Wq) {
    __shared__ float tile[32][33];
    int bx = blockIdx.x * 32, by = blockIdx.y * 32;
    int tx = threadIdx.x & 31, ty = threadIdx.x >> 5;
#pragma unroll
    for (int r = ty; r < 32; r += 8)
        tile[r][tx] = Wq[(by + r) * 512 + bx + tx];
    __syncthreads();
#pragma unroll
    for (int r = ty; r < 32; r += 8)
        g_WqT[(bx + r) * 512 + by + tx] = tile[tx][r];
}

// ---------------------------------------------------------------------------
// Kernel 1: e0[b,:] = (x[b,0,:] @ Wq) @ We, split-K second stage
// ---------------------------------------------------------------------------
__global__ void e0_kernel(const float* __restrict__ x,
                          const float* __restrict__ Wq,
                          const float* __restrict__ We) {
    int b = blockIdx.x;
    int tid = threadIdx.x;  // 512
    __shared__ float xs[QD_];
    __shared__ float q0[QD_];
    __shared__ float part[512];

    xs[tid] = x[(long)b * N_ * QD_ + tid];
    __syncthreads();

    {
        float acc = 0.f;
#pragma unroll 16
        for (int c = 0; c < QD_; c++)
            acc += xs[c] * Wq[c * INNER_ + tid];
        q0[tid] = acc;
    }
    __syncthreads();

    {
        int half = tid >> 8;     // 0/1
        int o = tid & 255;
        int c0 = half * 256;
        float acc = 0.f;
#pragma unroll 16
        for (int c = 0; c < 256; c++)
            acc += q0[c0 + c] * We[(c0 + c) * DR_ + o];
        part[tid] = acc;
    }
    __syncthreads();
    if (tid < DR_)
        g_e0[b * DR_ + tid] = part[tid] + part[tid + 256];
}

// ---------------------------------------------------------------------------
// Kernel 2: distance scan + local top-8. grid (DIST_BLOCKS, B), 256 thr.
// ---------------------------------------------------------------------------
__global__ void dist_topk_kernel(const float* __restrict__ ctx) {
    int b = blockIdx.y;
    int chunk = blockIdx.x;
    int tid = threadIdx.x;
    int warp = tid >> 5, lane = tid & 31;

    __shared__ float es[DR_];
    __shared__ float s_d2[8][TOPK_];
    __shared__ int   s_ix[8][TOPK_];

    if (tid < DR_) es[tid] = g_e0[b * DR_ + tid];
    __syncthreads();

    const float4* e4 = (const float4*)es;
    float4 ea = e4[lane];
    float4 eb = e4[lane + 32];

    float best[TOPK_];
    int   bidx[TOPK_];
#pragma unroll
    for (int i = 0; i < TOPK_; i++) { best[i] = 3.0e38f; bidx[i] = -1; }

    int row0 = chunk * 256 + warp * 32;
#pragma unroll 2
    for (int r = 0; r < 32; r++) {
        int row = row0 + r;
        const float4* crow = (const float4*)(ctx + ((long)b * M_ + row) * D_);
        float4 ca = crow[lane];
        float4 cb = crow[lane + 32];
        float dx, d2 = 0.f;
        dx = ca.x - ea.x; d2 += dx * dx;
        dx = ca.y - ea.y; d2 += dx * dx;
        dx = ca.z - ea.z; d2 += dx * dx;
        dx = ca.w - ea.w; d2 += dx * dx;
        dx = cb.x - eb.x; d2 += dx * dx;
        dx = cb.y - eb.y; d2 += dx * dx;
        dx = cb.z - eb.z; d2 += dx * dx;
        dx = cb.w - eb.w; d2 += dx * dx;
#pragma unroll
        for (int off = 16; off; off >>= 1)
            d2 += __shfl_down_sync(0xffffffffu, d2, off);
        if (lane == 0 && d2 < best[TOPK_ - 1]) {
            int p = TOPK_ - 1;
            while (p > 0 && best[p - 1] > d2) {
                best[p] = best[p - 1]; bidx[p] = bidx[p - 1]; p--;
            }
            best[p] = d2; bidx[p] = row;
        }
    }

    if (lane == 0) {
#pragma unroll
        for (int i = 0; i < TOPK_; i++) { s_d2[warp][i] = best[i]; s_ix[warp][i] = bidx[i]; }
    }
    __syncthreads();

    if (tid == 0) {
        float fb[TOPK_]; int fi[TOPK_];
#pragma unroll
        for (int i = 0; i < TOPK_; i++) { fb[i] = 3.0e38f; fi[i] = -1; }
        for (int w = 0; w < 8; w++)
            for (int i = 0; i < TOPK_; i++) {
                float d2 = s_d2[w][i];
                if (d2 < fb[TOPK_ - 1]) {
                    int ix = s_ix[w][i];
                    int p = TOPK_ - 1;
                    while (p > 0 && fb[p - 1] > d2) {
                        fb[p] = fb[p - 1]; fi[p] = fi[p - 1]; p--;
                    }
                    fb[p] = d2; fi[p] = ix;
                }
            }
        int off = (b * DIST_BLOCKS + chunk) * TOPK_;
        for (int i = 0; i < TOPK_; i++) { g_cand_d2[off + i] = fb[i]; g_cand_idx[off + i] = fi[i]; }
    }
}

// ---------------------------------------------------------------------------
// Kernel 3: parallel merge, register keys + shfl reduction. grid B, 256 thr.
// ---------------------------------------------------------------------------
__device__ __forceinline__ unsigned long long u64min(unsigned long long a,
                                                     unsigned long long b) {
    return a < b ? a : b;
}
__global__ void __launch_bounds__(256)
topk_merge_kernel() {
    int b = blockIdx.x;
    int tid = threadIdx.x;
    int lane = tid & 31, warp = tid >> 5;
    __shared__ unsigned long long warpmin[8];
    __shared__ unsigned long long winner;

    unsigned long long k[4];
    int base = b * NCAND;
#pragma unroll
    for (int s = 0; s < 4; s++) {
        int i = tid + s * 256;
        float d2 = g_cand_d2[base + i];
        int ix = g_cand_idx[base + i];
        k[s] = ((unsigned long long)__float_as_uint(d2) << 32) | (unsigned int)ix;
    }

    for (int sel = 0; sel < TOPK_; sel++) {
        unsigned long long m = u64min(u64min(k[0], k[1]), u64min(k[2], k[3]));
#pragma unroll
        for (int off = 16; off; off >>= 1)
            m = u64min(m, __shfl_down_sync(0xffffffffu, m, off));
        if (lane == 0) warpmin[warp] = m;
        __syncthreads();
        if (tid == 0) {
            unsigned long long w = warpmin[0];
#pragma unroll
            for (int i = 1; i < 8; i++) w = u64min(w, warpmin[i]);
            winner = w;
            g_topk_idx[b * TOPK_ + sel] = (int)(unsigned int)(w & 0xffffffffu);
        }
        __syncthreads();
        unsigned long long w = winner;
#pragma unroll
        for (int s = 0; s < 4; s++)
            if (k[s] == w) k[s] = ~0ULL;
        __syncthreads();
    }
}

// ---------------------------------------------------------------------------
// Kernel 4: fused gather + kv + kappa + vw.
// grid (4 slice, B), 512 thr, dyn smem 48KB. All 8 j handled per block so
// weight reads are shared.
// ---------------------------------------------------------------------------
__global__ void __launch_bounds__(512)
kw_kernel(const float* __restrict__ ctx,
          const float* __restrict__ Wk,
          const float* __restrict__ Wv,
          const float* __restrict__ Wout) {
    extern __shared__ float ksm[];
    float* rows = ksm;              // 8*512  (reps | labels)
    float* kv   = ksm + 4096;       // 8*512
    float* vv   = ksm + 8192;       // 8*512

    int slice = blockIdx.x, b = blockIdx.y;
    int tid = threadIdx.x;  // 512

#pragma unroll
    for (int j = 0; j < 8; j++) {
        int row = g_topk_idx[b * 8 + j];
        rows[j * 512 + tid] = ctx[((long)b * M_ + row) * D_ + tid];
    }
    __syncthreads();

    // kvec / vvec for all 8 j (coalesced weight reads shared across j)
    {
        float ak[8], av[8];
#pragma unroll
        for (int j = 0; j < 8; j++) { ak[j] = 0.f; av[j] = 0.f; }
#pragma unroll 4
        for (int r = 0; r < 256; r++) {
            float wk = Wk[r * 512 + tid];
            float wv = Wv[r * 512 + tid];
#pragma unroll
            for (int j = 0; j < 8; j++) {
                ak[j] += rows[j * 512 + 256 + r] * wk;  // labels
                av[j] += rows[j * 512 + r] * wv;        // reps
            }
        }
#pragma unroll
        for (int j = 0; j < 8; j++) {
            kv[j * 512 + tid] = ak[j];
            vv[j * 512 + tid] = av[j];
        }
    }
    __syncthreads();

    int hp = tid >> 7;             // 0..3
    int p  = slice * 128 + (tid & 127);

#pragma unroll
    for (int half = 0; half < 2; half++) {
        int h = hp + half * 4;
        // kappa: coalesced WqT column reads, shared across j
        {
            float aK[8];
#pragma unroll
            for (int j = 0; j < 8; j++) aK[j] = 0.f;
#pragma unroll 4
            for (int d = 0; d < 64; d++) {
                int i = h * 64 + d;
                float w = g_WqT[i * 512 + p];
#pragma unroll
                for (int j = 0; j < 8; j++) aK[j] += kv[j * 512 + i] * w;
            }
            long kbase = ((long)b * 512 + p) * 64 + h;
#pragma unroll
            for (int j = 0; j < 8; j++) g_kappa[kbase + j * 8] = aK[j] * SCALE_;
        }
        // vw: coalesced Wout column reads, shared across j
        {
            float aV[8];
#pragma unroll
            for (int j = 0; j < 8; j++) aV[j] = 0.f;
#pragma unroll 4
            for (int d = 0; d < 64; d++) {
                int i = h * 64 + d;
                float w = Wout[i * 512 + p];
#pragma unroll
                for (int j = 0; j < 8; j++) aV[j] += vv[j * 512 + i] * w;
            }
#pragma unroll
            for (int j = 0; j < 8; j++)
                g_vw[((long)b * 64 + j * 8 + h) * 512 + p] = aV[j];
        }
    }
}

// ---------------------------------------------------------------------------
// Kernel 5: fused sim + softmax + out, f32x2 FMA.
// grid (16 nchunk, B), 256 thr, 128-token tile, single wave (128 blocks).
// ---------------------------------------------------------------------------
#define STR_T 132   // token-stride for transposed tiles (16B aligned, low-conflict)
#define STR_C 68

__global__ void __launch_bounds__(256)
fused_attn(const float* __restrict__ x,
           float* __restrict__ out,
           const float* __restrict__ bout) {
    extern __shared__ float fsm[];
    float* bufA = fsm;           // 64*132 = 8448 floats: xsT, then aT (in place)
    float* bufC = fsm + 8448;    // 64*68  = 4352 floats: ks, then vws

    int nc = blockIdx.x, b = blockIdx.y;
    int n0 = nc * 128;
    int tid = threadIdx.x;
    int ty = tid >> 4, tx = tid & 15;  // 8 tokens x 4 cols per thread
    int tok0 = ty * 8;

    const float* xb = x + ((long)b * N_ + n0) * QD_;
    const float* kb = g_kappa + (long)b * QD_ * 64;

    unsigned long long acc[4][4];
#pragma unroll
    for (int t = 0; t < 4; t++)
#pragma unroll
        for (int c = 0; c < 4; c++) acc[t][c] = 0ULL;

    // ---- phase 1: sim = x @ kappa (k-chunks of 64) ----
    for (int pc = 0; pc < 8; pc++) {
        int p0 = pc * 64;
        // stage x transposed: xsT[k][token]
#pragma unroll
        for (int l = 0; l < 8; l++) {
            int f = tid + l * 256;
            int row = f >> 4, kc4 = (f & 15) * 4;
            float4 v = *(const float4*)(xb + (long)row * QD_ + p0 + kc4);
            bufA[(kc4 + 0) * STR_T + row] = v.x;
            bufA[(kc4 + 1) * STR_T + row] = v.y;
            bufA[(kc4 + 2) * STR_T + row] = v.z;
            bufA[(kc4 + 3) * STR_T + row] = v.w;
        }
        // stage kappa chunk: ks[k][c]
#pragma unroll
        for (int l = 0; l < 4; l++) {
            int f = tid + l * 256;
            int row = f >> 4, c4 = (f & 15) * 4;
            *(float4*)&bufC[row * STR_C + c4] =
                *(const float4*)(kb + (long)(p0 + row) * 64 + c4);
        }
        __syncthreads();
#pragma unroll 8
        for (int kk = 0; kk < 64; kk++) {
            const ulonglong2* ap = (const ulonglong2*)&bufA[kk * STR_T + tok0];
            ulonglong2 a01 = ap[0];
            ulonglong2 a23 = ap[1];
            float4 bq = *(const float4*)&bufC[kk * STR_C + tx * 4];
            unsigned long long b0 = splat2(bq.x), b1 = splat2(bq.y),
                               b2 = splat2(bq.z), b3 = splat2(bq.w);
            fma2(acc[0][0], a01.x, b0); fma2(acc[0][1], a01.x, b1);
            fma2(acc[0][2], a01.x, b2); fma2(acc[0][3], a01.x, b3);
            fma2(acc[1][0], a01.y, b0); fma2(acc[1][1], a01.y, b1);
            fma2(acc[1][2], a01.y, b2); fma2(acc[1][3], a01.y, b3);
            fma2(acc[2][0], a23.x, b0); fma2(acc[2][1], a23.x, b1);
            fma2(acc[2][2], a23.x, b2); fma2(acc[2][3], a23.x, b3);
            fma2(acc[3][0], a23.y, b0); fma2(acc[3][1], a23.y, b1);
            fma2(acc[3][2], a23.y, b2); fma2(acc[3][3], a23.y, b3);
        }
        __syncthreads();
    }

    // ---- dump sim transposed into bufA as aT[c][token] ----
#pragma unroll
    for (int t = 0; t < 4; t++)
#pragma unroll
        for (int c = 0; c < 4; c++) {
            float2 f = unpack2(acc[t][c]);
            int cc = tx * 4 + c;
            bufA[cc * STR_T + tok0 + 2 * t]     = f.x;
            bufA[cc * STR_T + tok0 + 2 * t + 1] = f.y;
        }
    __syncthreads();

    // ---- softmax in place over j (cols h, h+8, ..., h+56) ----
#pragma unroll
    for (int s = 0; s < 4; s++) {
        int task = s * 256 + tid;      // 0..1023 = token*8 + head
        int t = task >> 3, h = task & 7;
        float v[8];
#pragma unroll
        for (int j = 0; j < 8; j++) v[j] = bufA[(j * 8 + h) * STR_T + t];
        float m = v[0];
#pragma unroll
        for (int j = 1; j < 8; j++) m = fmaxf(m, v[j]);
        float e[8], sum = 0.f;
#pragma unroll
        for (int j = 0; j < 8; j++) { e[j] = __expf(v[j] - m); sum += e[j]; }
        float inv = 1.f / sum;
#pragma unroll
        for (int j = 0; j < 8; j++) bufA[(j * 8 + h) * STR_T + t] = e[j] * inv;
    }
    __syncthreads();

    // ---- phase 3: out = a @ vw + bias (8 o-chunks of 64) ----
    const float* vwb = g_vw + (long)b * 64 * 512;
    float* ob = out + ((long)b * N_ + n0) * 512;

    for (int oc = 0; oc < 8; oc++) {
        int o0 = oc * 64;
#pragma unroll
        for (int l = 0; l < 4; l++) {
            int f = tid + l * 256;
            int row = f >> 4, c4 = (f & 15) * 4;
            *(float4*)&bufC[row * STR_C + c4] =
                *(const float4*)(vwb + (long)row * 512 + o0 + c4);
        }
#pragma unroll
        for (int t = 0; t < 4; t++)
#pragma unroll
            for (int c = 0; c < 4; c++) acc[t][c] = 0ULL;
        __syncthreads();

#pragma unroll 8
        for (int cc = 0; cc < 64; cc++) {
            const ulonglong2* ap = (const ulonglong2*)&bufA[cc * STR_T + tok0];
            ulonglong2 a01 = ap[0];
            ulonglong2 a23 = ap[1];
            float4 bq = *(const float4*)&bufC[cc * STR_C + tx * 4];
            unsigned long long b0 = splat2(bq.x), b1 = splat2(bq.y),
                               b2 = splat2(bq.z), b3 = splat2(bq.w);
            fma2(acc[0][0], a01.x, b0); fma2(acc[0][1], a01.x, b1);
            fma2(acc[0][2], a01.x, b2); fma2(acc[0][3], a01.x, b3);
            fma2(acc[1][0], a01.y, b0); fma2(acc[1][1], a01.y, b1);
            fma2(acc[1][2], a01.y, b2); fma2(acc[1][3], a01.y, b3);
            fma2(acc[2][0], a23.x, b0); fma2(acc[2][1], a23.x, b1);
            fma2(acc[2][2], a23.x, b2); fma2(acc[2][3], a23.x, b3);
            fma2(acc[3][0], a23.y, b0); fma2(acc[3][1], a23.y, b1);
            fma2(acc[3][2], a23.y, b2); fma2(acc[3][3], a23.y, b3);
        }

        float4 bias4 = *(const float4*)(bout + o0 + tx * 4);
#pragma unroll
        for (int t = 0; t < 4; t++) {
            float2 f0 = unpack2(acc[t][0]);
            float2 f1 = unpack2(acc[t][1]);
            float2 f2 = unpack2(acc[t][2]);
            float2 f3 = unpack2(acc[t][3]);
            int tokA = tok0 + 2 * t;
            float4 r0 = make_float4(f0.x + bias4.x, f1.x + bias4.y,
                                    f2.x + bias4.z, f3.x + bias4.w);
            float4 r1 = make_float4(f0.y + bias4.x, f1.y + bias4.y,
                                    f2.y + bias4.z, f3.y + bias4.w);
            *(float4*)(ob + (long)tokA * 512 + o0 + tx * 4)       = r0;
            *(float4*)(ob + (long)(tokA + 1) * 512 + o0 + tx * 4) = r1;
        }
        __syncthreads();
    }
}

// ---------------------------------------------------------------------------
// Launch
// ---------------------------------------------------------------------------
extern "C" void kernel_launch(void* const* d_in, const int* in_sizes, int n_in,
                              void* d_out, int out_size) {
    const float* x    = (const float*)d_in[0];
    const float* ctx  = (const float*)d_in[1];
    const float* Wq   = (const float*)d_in[2];
    const float* Wk   = (const float*)d_in[3];
    const float* Wv   = (const float*)d_in[4];
    const float* We   = (const float*)d_in[5];
    const float* Wout = (const float*)d_in[6];
    const float* bout = (const float*)d_in[7];
    float* out = (float*)d_out;

    const int KW_SMEM = 3 * 4096 * sizeof(float);          // 48 KB
    const int FA_SMEM = (8448 + 4352) * sizeof(float);     // ~51.2 KB
    cudaFuncSetAttribute(kw_kernel,
                         cudaFuncAttributeMaxDynamicSharedMemorySize, KW_SMEM);
    cudaFuncSetAttribute(fused_attn,
                         cudaFuncAttributeMaxDynamicSharedMemorySize, FA_SMEM);

    transpose512<<<dim3(16, 16), 256>>>(Wq);
    e0_kernel<<<B_, 512>>>(x, Wq, We);
    dist_topk_kernel<<<dim3(DIST_BLOCKS, B_), 256>>>(ctx);
    topk_merge_kernel<<<B_, 256>>>();
    kw_kernel<<<dim3(4, B_), 512, KW_SMEM>>>(ctx, Wk, Wv, Wout);
    fused_attn<<<dim3(16, B_), 256, FA_SMEM>>>(x, out, bout);
}

// round 9
// speedup vs baseline: 1.0074x; 1.0074x over previous
#include <cuda_runtime.h>
#include <math.h>

// ---------------------------------------------------------------------------
// Problem constants
// ---------------------------------------------------------------------------
#define B_     8
#define N_     2048
#define M_     32768
#define QD_    512
#define DR_    256
#define D_     512
#define H_     8
#define DH_    64
#define INNER_ 512
#define TOPK_  8
#define SCALE_ 0.125f

#define DIST_BLOCKS 128
#define NCAND (DIST_BLOCKS * TOPK_)   // 1024

// ---------------------------------------------------------------------------
// Scratch
// ---------------------------------------------------------------------------
__device__ float g_e0[B_ * DR_];
__device__ float g_cand_d2[B_ * NCAND];
__device__ int   g_cand_idx[B_ * NCAND];
__device__ int   g_topk_idx[B_ * TOPK_];
__device__ float g_WqT[QD_ * INNER_];     // WqT[i][p] = Wq[p][i]
__device__ float g_kappa[B_ * QD_ * 64];  // [b][p][c], c=j*8+h (SCALE folded)
__device__ float g_vw[B_ * 64 * INNER_];  // [b][c][o]

// ---------------------------------------------------------------------------
// f32x2 helpers
// ---------------------------------------------------------------------------
__device__ __forceinline__ unsigned long long splat2(float f) {
    unsigned long long r;
    asm("mov.b64 %0, {%1, %1};" : "=l"(r) : "f"(f));
    return r;
}
__device__ __forceinline__ void fma2(unsigned long long& d,
                                     unsigned long long a,
                                     unsigned long long b) {
    asm("fma.rn.f32x2 %0, %1, %2, %0;" : "+l"(d) : "l"(a), "l"(b));
}
__device__ __forceinline__ float2 unpack2(unsigned long long v) {
    float2 r;
    asm("mov.b64 {%0, %1}, %2;" : "=f"(r.x), "=f"(r.y) : "l"(v));
    return r;
}

// ---------------------------------------------------------------------------
// Kernel 0: transpose Wq -> g_WqT
// ---------------------------------------------------------------------------
__global__ void transpose512(const float* __restrict__ Wq) {
    __shared__ float tile[32][33];
    int bx = blockIdx.x * 32, by = blockIdx.y * 32;
    int tx = threadIdx.x & 31, ty = threadIdx.x >> 5;
#pragma unroll
    for (int r = ty; r < 32; r += 8)
        tile[r][tx] = Wq[(by + r) * 512 + bx + tx];
    __syncthreads();
#pragma unroll
    for (int r = ty; r < 32; r += 8)
        g_WqT[(bx + r) * 512 + by + tx] = tile[tx][r];
}

// ---------------------------------------------------------------------------
// Kernel 1: e0[b,:] = (x[b,0,:] @ Wq) @ We, split-K second stage
// ---------------------------------------------------------------------------
__global__ void e0_kernel(const float* __restrict__ x,
                          const float* __restrict__ Wq,
                          const float* __restrict__ We) {
    int b = blockIdx.x;
    int tid = threadIdx.x;  // 512
    __shared__ float xs[QD_];
    __shared__ float q0[QD_];
    __shared__ float part[512];

    xs[tid] = x[(long)b * N_ * QD_ + tid];
    __syncthreads();

    {
        float acc = 0.f;
#pragma unroll 16
        for (int c = 0; c < QD_; c++)
            acc += xs[c] * Wq[c * INNER_ + tid];
        q0[tid] = acc;
    }
    __syncthreads();

    {
        int half = tid >> 8;     // 0/1
        int o = tid & 255;
        int c0 = half * 256;
        float acc = 0.f;
#pragma unroll 16
        for (int c = 0; c < 256; c++)
            acc += q0[c0 + c] * We[(c0 + c) * DR_ + o];
        part[tid] = acc;
    }
    __syncthreads();
    if (tid < DR_)
        g_e0[b * DR_ + tid] = part[tid] + part[tid + 256];
}

// ---------------------------------------------------------------------------
// Kernel 2: distance scan + local top-8. grid (DIST_BLOCKS, B), 256 thr.
// ---------------------------------------------------------------------------
__global__ void dist_topk_kernel(const float* __restrict__ ctx) {
    int b = blockIdx.y;
    int chunk = blockIdx.x;
    int tid = threadIdx.x;
    int warp = tid >> 5, lane = tid & 31;

    __shared__ float es[DR_];
    __shared__ float s_d2[8][TOPK_];
    __shared__ int   s_ix[8][TOPK_];

    if (tid < DR_) es[tid] = g_e0[b * DR_ + tid];
    __syncthreads();

    const float4* e4 = (const float4*)es;
    float4 ea = e4[lane];
    float4 eb = e4[lane + 32];

    float best[TOPK_];
    int   bidx[TOPK_];
#pragma unroll
    for (int i = 0; i < TOPK_; i++) { best[i] = 3.0e38f; bidx[i] = -1; }

    int row0 = chunk * 256 + warp * 32;
#pragma unroll 2
    for (int r = 0; r < 32; r++) {
        int row = row0 + r;
        const float4* crow = (const float4*)(ctx + ((long)b * M_ + row) * D_);
        float4 ca = crow[lane];
        float4 cb = crow[lane + 32];
        float dx, d2 = 0.f;
        dx = ca.x - ea.x; d2 += dx * dx;
        dx = ca.y - ea.y; d2 += dx * dx;
        dx = ca.z - ea.z; d2 += dx * dx;
        dx = ca.w - ea.w; d2 += dx * dx;
        dx = cb.x - eb.x; d2 += dx * dx;
        dx = cb.y - eb.y; d2 += dx * dx;
        dx = cb.z - eb.z; d2 += dx * dx;
        dx = cb.w - eb.w; d2 += dx * dx;
#pragma unroll
        for (int off = 16; off; off >>= 1)
            d2 += __shfl_down_sync(0xffffffffu, d2, off);
        if (lane == 0 && d2 < best[TOPK_ - 1]) {
            int p = TOPK_ - 1;
            while (p > 0 && best[p - 1] > d2) {
                best[p] = best[p - 1]; bidx[p] = bidx[p - 1]; p--;
            }
            best[p] = d2; bidx[p] = row;
        }
    }

    if (lane == 0) {
#pragma unroll
        for (int i = 0; i < TOPK_; i++) { s_d2[warp][i] = best[i]; s_ix[warp][i] = bidx[i]; }
    }
    __syncthreads();

    if (tid == 0) {
        float fb[TOPK_]; int fi[TOPK_];
#pragma unroll
        for (int i = 0; i < TOPK_; i++) { fb[i] = 3.0e38f; fi[i] = -1; }
        for (int w = 0; w < 8; w++)
            for (int i = 0; i < TOPK_; i++) {
                float d2 = s_d2[w][i];
                if (d2 < fb[TOPK_ - 1]) {
                    int ix = s_ix[w][i];
                    int p = TOPK_ - 1;
                    while (p > 0 && fb[p - 1] > d2) {
                        fb[p] = fb[p - 1]; fi[p] = fi[p - 1]; p--;
                    }
                    fb[p] = d2; fi[p] = ix;
                }
            }
        int off = (b * DIST_BLOCKS + chunk) * TOPK_;
        for (int i = 0; i < TOPK_; i++) { g_cand_d2[off + i] = fb[i]; g_cand_idx[off + i] = fi[i]; }
    }
}

// ---------------------------------------------------------------------------
// Kernel 3: parallel merge, register keys + shfl reduction. grid B, 256 thr.
// ---------------------------------------------------------------------------
__device__ __forceinline__ unsigned long long u64min(unsigned long long a,
                                                     unsigned long long b) {
    return a < b ? a : b;
}
__global__ void __launch_bounds__(256)
topk_merge_kernel() {
    int b = blockIdx.x;
    int tid = threadIdx.x;
    int lane = tid & 31, warp = tid >> 5;
    __shared__ unsigned long long warpmin[8];
    __shared__ unsigned long long winner;

    unsigned long long k[4];
    int base = b * NCAND;
#pragma unroll
    for (int s = 0; s < 4; s++) {
        int i = tid + s * 256;
        float d2 = g_cand_d2[base + i];
        int ix = g_cand_idx[base + i];
        k[s] = ((unsigned long long)__float_as_uint(d2) << 32) | (unsigned int)ix;
    }

    for (int sel = 0; sel < TOPK_; sel++) {
        unsigned long long m = u64min(u64min(k[0], k[1]), u64min(k[2], k[3]));
#pragma unroll
        for (int off = 16; off; off >>= 1)
            m = u64min(m, __shfl_down_sync(0xffffffffu, m, off));
        if (lane == 0) warpmin[warp] = m;
        __syncthreads();
        if (tid == 0) {
            unsigned long long w = warpmin[0];
#pragma unroll
            for (int i = 1; i < 8; i++) w = u64min(w, warpmin[i]);
            winner = w;
            g_topk_idx[b * TOPK_ + sel] = (int)(unsigned int)(w & 0xffffffffu);
        }
        __syncthreads();
        unsigned long long w = winner;
#pragma unroll
        for (int s = 0; s < 4; s++)
            if (k[s] == w) k[s] = ~0ULL;
        __syncthreads();
    }
}

// ---------------------------------------------------------------------------
// Kernel 4: fused gather + kv + kappa + vw.
// grid (4 slice, B), 512 thr, dyn smem 48KB. All 8 j handled per block so
// weight reads are shared.
// ---------------------------------------------------------------------------
__global__ void __launch_bounds__(512)
kw_kernel(const float* __restrict__ ctx,
          const float* __restrict__ Wk,
          const float* __restrict__ Wv,
          const float* __restrict__ Wout) {
    extern __shared__ float ksm[];
    float* rows = ksm;              // 8*512  (reps | labels)
    float* kv   = ksm + 4096;       // 8*512
    float* vv   = ksm + 8192;       // 8*512

    int slice = blockIdx.x, b = blockIdx.y;
    int tid = threadIdx.x;  // 512

#pragma unroll
    for (int j = 0; j < 8; j++) {
        int row = g_topk_idx[b * 8 + j];
        rows[j * 512 + tid] = ctx[((long)b * M_ + row) * D_ + tid];
    }
    __syncthreads();

    // kvec / vvec for all 8 j (coalesced weight reads shared across j)
    {
        float ak[8], av[8];
#pragma unroll
        for (int j = 0; j < 8; j++) { ak[j] = 0.f; av[j] = 0.f; }
#pragma unroll 4
        for (int r = 0; r < 256; r++) {
            float wk = Wk[r * 512 + tid];
            float wv = Wv[r * 512 + tid];
#pragma unroll
            for (int j = 0; j < 8; j++) {
                ak[j] += rows[j * 512 + 256 + r] * wk;  // labels
                av[j] += rows[j * 512 + r] * wv;        // reps
            }
        }
#pragma unroll
        for (int j = 0; j < 8; j++) {
            kv[j * 512 + tid] = ak[j];
            vv[j * 512 + tid] = av[j];
        }
    }
    __syncthreads();

    int hp = tid >> 7;             // 0..3
    int p  = slice * 128 + (tid & 127);

#pragma unroll
    for (int half = 0; half < 2; half++) {
        int h = hp + half * 4;
        // kappa: coalesced WqT column reads, shared across j
        {
            float aK[8];
#pragma unroll
            for (int j = 0; j < 8; j++) aK[j] = 0.f;
#pragma unroll 4
            for (int d = 0; d < 64; d++) {
                int i = h * 64 + d;
                float w = g_WqT[i * 512 + p];
#pragma unroll
                for (int j = 0; j < 8; j++) aK[j] += kv[j * 512 + i] * w;
            }
            long kbase = ((long)b * 512 + p) * 64 + h;
#pragma unroll
            for (int j = 0; j < 8; j++) g_kappa[kbase + j * 8] = aK[j] * SCALE_;
        }
        // vw: coalesced Wout column reads, shared across j
        {
            float aV[8];
#pragma unroll
            for (int j = 0; j < 8; j++) aV[j] = 0.f;
#pragma unroll 4
            for (int d = 0; d < 64; d++) {
                int i = h * 64 + d;
                float w = Wout[i * 512 + p];
#pragma unroll
                for (int j = 0; j < 8; j++) aV[j] += vv[j * 512 + i] * w;
            }
#pragma unroll
            for (int j = 0; j < 8; j++)
                g_vw[((long)b * 64 + j * 8 + h) * 512 + p] = aV[j];
        }
    }
}

// ---------------------------------------------------------------------------
// Kernel 5: fused sim + softmax + out, f32x2 FMA.
// grid (16 nchunk, B), 256 thr, 128-token tile, single wave (128 blocks).
// ---------------------------------------------------------------------------
#define STR_T 132   // token-stride for transposed tiles (16B aligned, low-conflict)
#define STR_C 68

__global__ void __launch_bounds__(256)
fused_attn(const float* __restrict__ x,
           float* __restrict__ out,
           const float* __restrict__ bout) {
    extern __shared__ float fsm[];
    float* bufA = fsm;           // 64*132 = 8448 floats: xsT, then aT (in place)
    float* bufC = fsm + 8448;    // 64*68  = 4352 floats: ks, then vws

    int nc = blockIdx.x, b = blockIdx.y;
    int n0 = nc * 128;
    int tid = threadIdx.x;
    int ty = tid >> 4, tx = tid & 15;  // 8 tokens x 4 cols per thread
    int tok0 = ty * 8;

    const float* xb = x + ((long)b * N_ + n0) * QD_;
    const float* kb = g_kappa + (long)b * QD_ * 64;

    unsigned long long acc[4][4];
#pragma unroll
    for (int t = 0; t < 4; t++)
#pragma unroll
        for (int c = 0; c < 4; c++) acc[t][c] = 0ULL;

    // ---- phase 1: sim = x @ kappa (k-chunks of 64) ----
    for (int pc = 0; pc < 8; pc++) {
        int p0 = pc * 64;
        // stage x transposed: xsT[k][token]
#pragma unroll
        for (int l = 0; l < 8; l++) {
            int f = tid + l * 256;
            int row = f >> 4, kc4 = (f & 15) * 4;
            float4 v = *(const float4*)(xb + (long)row * QD_ + p0 + kc4);
            bufA[(kc4 + 0) * STR_T + row] = v.x;
            bufA[(kc4 + 1) * STR_T + row] = v.y;
            bufA[(kc4 + 2) * STR_T + row] = v.z;
            bufA[(kc4 + 3) * STR_T + row] = v.w;
        }
        // stage kappa chunk: ks[k][c]
#pragma unroll
        for (int l = 0; l < 4; l++) {
            int f = tid + l * 256;
            int row = f >> 4, c4 = (f & 15) * 4;
            *(float4*)&bufC[row * STR_C + c4] =
                *(const float4*)(kb + (long)(p0 + row) * 64 + c4);
        }
        __syncthreads();
#pragma unroll 8
        for (int kk = 0; kk < 64; kk++) {
            const ulonglong2* ap = (const ulonglong2*)&bufA[kk * STR_T + tok0];
            ulonglong2 a01 = ap[0];
            ulonglong2 a23 = ap[1];
            float4 bq = *(const float4*)&bufC[kk * STR_C + tx * 4];
            unsigned long long b0 = splat2(bq.x), b1 = splat2(bq.y),
                               b2 = splat2(bq.z), b3 = splat2(bq.w);
            fma2(acc[0][0], a01.x, b0); fma2(acc[0][1], a01.x, b1);
            fma2(acc[0][2], a01.x, b2); fma2(acc[0][3], a01.x, b3);
            fma2(acc[1][0], a01.y, b0); fma2(acc[1][1], a01.y, b1);
            fma2(acc[1][2], a01.y, b2); fma2(acc[1][3], a01.y, b3);
            fma2(acc[2][0], a23.x, b0); fma2(acc[2][1], a23.x, b1);
            fma2(acc[2][2], a23.x, b2); fma2(acc[2][3], a23.x, b3);
            fma2(acc[3][0], a23.y, b0); fma2(acc[3][1], a23.y, b1);
            fma2(acc[3][2], a23.y, b2); fma2(acc[3][3], a23.y, b3);
        }
        __syncthreads();
    }

    // ---- dump sim transposed into bufA as aT[c][token] ----
#pragma unroll
    for (int t = 0; t < 4; t++)
#pragma unroll
        for (int c = 0; c < 4; c++) {
            float2 f = unpack2(acc[t][c]);
            int cc = tx * 4 + c;
            bufA[cc * STR_T + tok0 + 2 * t]     = f.x;
            bufA[cc * STR_T + tok0 + 2 * t + 1] = f.y;
        }
    __syncthreads();

    // ---- softmax in place over j (cols h, h+8, ..., h+56) ----
#pragma unroll
    for (int s = 0; s < 4; s++) {
        int task = s * 256 + tid;      // 0..1023 = token*8 + head
        int t = task >> 3, h = task & 7;
        float v[8];
#pragma unroll
        for (int j = 0; j < 8; j++) v[j] = bufA[(j * 8 + h) * STR_T + t];
        float m = v[0];
#pragma unroll
        for (int j = 1; j < 8; j++) m = fmaxf(m, v[j]);
        float e[8], sum = 0.f;
#pragma unroll
        for (int j = 0; j < 8; j++) { e[j] = __expf(v[j] - m); sum += e[j]; }
        float inv = 1.f / sum;
#pragma unroll
        for (int j = 0; j < 8; j++) bufA[(j * 8 + h) * STR_T + t] = e[j] * inv;
    }
    __syncthreads();

    // ---- phase 3: out = a @ vw + bias (8 o-chunks of 64) ----
    const float* vwb = g_vw + (long)b * 64 * 512;
    float* ob = out + ((long)b * N_ + n0) * 512;

    for (int oc = 0; oc < 8; oc++) {
        int o0 = oc * 64;
#pragma unroll
        for (int l = 0; l < 4; l++) {
            int f = tid + l * 256;
            int row = f >> 4, c4 = (f & 15) * 4;
            *(float4*)&bufC[row * STR_C + c4] =
                *(const float4*)(vwb + (long)row * 512 + o0 + c4);
        }
#pragma unroll
        for (int t = 0; t < 4; t++)
#pragma unroll
            for (int c = 0; c < 4; c++) acc[t][c] = 0ULL;
        __syncthreads();

#pragma unroll 8
        for (int cc = 0; cc < 64; cc++) {
            const ulonglong2* ap = (const ulonglong2*)&bufA[cc * STR_T + tok0];
            ulonglong2 a01 = ap[0];
            ulonglong2 a23 = ap[1];
            float4 bq = *(const float4*)&bufC[cc * STR_C + tx * 4];
            unsigned long long b0 = splat2(bq.x), b1 = splat2(bq.y),
                               b2 = splat2(bq.z), b3 = splat2(bq.w);
            fma2(acc[0][0], a01.x, b0); fma2(acc[0][1], a01.x, b1);
            fma2(acc[0][2], a01.x, b2); fma2(acc[0][3], a01.x, b3);
            fma2(acc[1][0], a01.y, b0); fma2(acc[1][1], a01.y, b1);
            fma2(acc[1][2], a01.y, b2); fma2(acc[1][3], a01.y, b3);
            fma2(acc[2][0], a23.x, b0); fma2(acc[2][1], a23.x, b1);
            fma2(acc[2][2], a23.x, b2); fma2(acc[2][3], a23.x, b3);
            fma2(acc[3][0], a23.y, b0); fma2(acc[3][1], a23.y, b1);
            fma2(acc[3][2], a23.y, b2); fma2(acc[3][3], a23.y, b3);
        }

        float4 bias4 = *(const float4*)(bout + o0 + tx * 4);
#pragma unroll
        for (int t = 0; t < 4; t++) {
            float2 f0 = unpack2(acc[t][0]);
            float2 f1 = unpack2(acc[t][1]);
            float2 f2 = unpack2(acc[t][2]);
            float2 f3 = unpack2(acc[t][3]);
            int tokA = tok0 + 2 * t;
            float4 r0 = make_float4(f0.x + bias4.x, f1.x + bias4.y,
                                    f2.x + bias4.z, f3.x + bias4.w);
            float4 r1 = make_float4(f0.y + bias4.x, f1.y + bias4.y,
                                    f2.y + bias4.z, f3.y + bias4.w);
            *(float4*)(ob + (long)tokA * 512 + o0 + tx * 4)       = r0;
            *(float4*)(ob + (long)(tokA + 1) * 512 + o0 + tx * 4) = r1;
        }
        __syncthreads();
    }
}

// ---------------------------------------------------------------------------
// Launch
// ---------------------------------------------------------------------------
extern "C" void kernel_launch(void* const* d_in, const int* in_sizes, int n_in,
                              void* d_out, int out_size) {
    const float* x    = (const float*)d_in[0];
    const float* ctx  = (const float*)d_in[1];
    const float* Wq   = (const float*)d_in[2];
    const float* Wk   = (const float*)d_in[3];
    const float* Wv   = (const float*)d_in[4];
    const float* We   = (const float*)d_in[5];
    const float* Wout = (const float*)d_in[6];
    const float* bout = (const float*)d_in[7];
    float* out = (float*)d_out;

    const int KW_SMEM = 3 * 4096 * sizeof(float);          // 48 KB
    const int FA_SMEM = (8448 + 4352) * sizeof(float);     // ~51.2 KB
    cudaFuncSetAttribute(kw_kernel,
                         cudaFuncAttributeMaxDynamicSharedMemorySize, KW_SMEM);
    cudaFuncSetAttribute(fused_attn,
                         cudaFuncAttributeMaxDynamicSharedMemorySize, FA_SMEM);

    transpose512<<<dim3(16, 16), 256>>>(Wq);
    e0_kernel<<<B_, 512>>>(x, Wq, We);
    dist_topk_kernel<<<dim3(DIST_BLOCKS, B_), 256>>>(ctx);
    topk_merge_kernel<<<B_, 256>>>();
    kw_kernel<<<dim3(4, B_), 512, KW_SMEM>>>(ctx, Wk, Wv, Wout);
    fused_attn<<<dim3(16, B_), 256, FA_SMEM>>>(x, out, bout);
}

// round 10
// speedup vs baseline: 1.0408x; 1.0332x over previous
#include <cuda_runtime.h>
#include <math.h>

// ---------------------------------------------------------------------------
// Problem constants
// ---------------------------------------------------------------------------
#define B_     8
#define N_     2048
#define M_     32768
#define QD_    512
#define DR_    256
#define D_     512
#define H_     8
#define DH_    64
#define INNER_ 512
#define TOPK_  8
#define SCALE_ 0.125f

#define DIST_BLOCKS 128
#define NCAND (DIST_BLOCKS * TOPK_)   // 1024

// ---------------------------------------------------------------------------
// Scratch
// ---------------------------------------------------------------------------
__device__ float g_e0[B_ * DR_];
__device__ float g_cand_d2[B_ * NCAND];
__device__ int   g_cand_idx[B_ * NCAND];
__device__ int   g_topk_idx[B_ * TOPK_];
__device__ float g_WqT[QD_ * INNER_];     // WqT[i][p] = Wq[p][i]
__device__ float g_kappa[B_ * QD_ * 64];  // [b][p][c], c=j*8+h (SCALE folded)
__device__ float g_vw[B_ * 64 * INNER_];  // [b][c][o]
__device__ unsigned int g_done[B_];       // zero-init; reset by last block

// ---------------------------------------------------------------------------
// f32x2 helpers
// ---------------------------------------------------------------------------
__device__ __forceinline__ unsigned long long splat2(float f) {
    unsigned long long r;
    asm("mov.b64 %0, {%1, %1};" : "=l"(r) : "f"(f));
    return r;
}
__device__ __forceinline__ void fma2(unsigned long long& d,
                                     unsigned long long a,
                                     unsigned long long b) {
    asm("fma.rn.f32x2 %0, %1, %2, %0;" : "+l"(d) : "l"(a), "l"(b));
}
__device__ __forceinline__ float2 unpack2(unsigned long long v) {
    float2 r;
    asm("mov.b64 {%0, %1}, %2;" : "=f"(r.x), "=f"(r.y) : "l"(v));
    return r;
}
__device__ __forceinline__ unsigned long long u64min(unsigned long long a,
                                                     unsigned long long b) {
    return a < b ? a : b;
}

// ---------------------------------------------------------------------------
// Kernel 0: transpose Wq -> g_WqT
// ---------------------------------------------------------------------------
__global__ void transpose512(const float* __restrict__ Wq) {
    __shared__ float tile[32][33];
    int bx = blockIdx.x * 32, by = blockIdx.y * 32;
    int tx = threadIdx.x & 31, ty = threadIdx.x >> 5;
#pragma unroll
    for (int r = ty; r < 32; r += 8)
        tile[r][tx] = Wq[(by + r) * 512 + bx + tx];
    __syncthreads();
#pragma unroll
    for (int r = ty; r < 32; r += 8)
        g_WqT[(bx + r) * 512 + by + tx] = tile[tx][r];
}

// ---------------------------------------------------------------------------
// Kernel 1: e0[b,:] = (x[b,0,:] @ Wq) @ We, split-K second stage
// ---------------------------------------------------------------------------
__global__ void e0_kernel(const float* __restrict__ x,
                          const float* __restrict__ Wq,
                          const float* __restrict__ We) {
    int b = blockIdx.x;
    int tid = threadIdx.x;  // 512
    __shared__ float xs[QD_];
    __shared__ float q0[QD_];
    __shared__ float part[512];

    xs[tid] = x[(long)b * N_ * QD_ + tid];
    __syncthreads();

    {
        float acc = 0.f;
#pragma unroll 16
        for (int c = 0; c < QD_; c++)
            acc += xs[c] * Wq[c * INNER_ + tid];
        q0[tid] = acc;
    }
    __syncthreads();

    {
        int half = tid >> 8;
        int o = tid & 255;
        int c0 = half * 256;
        float acc = 0.f;
#pragma unroll 16
        for (int c = 0; c < 256; c++)
            acc += q0[c0 + c] * We[(c0 + c) * DR_ + o];
        part[tid] = acc;
    }
    __syncthreads();
    if (tid < DR_)
        g_e0[b * DR_ + tid] = part[tid] + part[tid + 256];
}

// ---------------------------------------------------------------------------
// Kernel 2: distance scan + local top-8 + LAST-BLOCK global merge.
// grid (DIST_BLOCKS, B), 256 thr.
// ---------------------------------------------------------------------------
__global__ void dist_topk_kernel(const float* __restrict__ ctx) {
    int b = blockIdx.y;
    int chunk = blockIdx.x;
    int tid = threadIdx.x;
    int warp = tid >> 5, lane = tid & 31;

    __shared__ float es[DR_];
    __shared__ float s_d2[8][TOPK_];
    __shared__ int   s_ix[8][TOPK_];
    __shared__ int   s_last;

    if (tid < DR_) es[tid] = g_e0[b * DR_ + tid];
    __syncthreads();

    const float4* e4 = (const float4*)es;
    float4 ea = e4[lane];
    float4 eb = e4[lane + 32];

    float best[TOPK_];
    int   bidx[TOPK_];
#pragma unroll
    for (int i = 0; i < TOPK_; i++) { best[i] = 3.0e38f; bidx[i] = -1; }

    int row0 = chunk * 256 + warp * 32;
#pragma unroll 2
    for (int r = 0; r < 32; r++) {
        int row = row0 + r;
        const float4* crow = (const float4*)(ctx + ((long)b * M_ + row) * D_);
        float4 ca = crow[lane];
        float4 cb = crow[lane + 32];
        float dx, d2 = 0.f;
        dx = ca.x - ea.x; d2 += dx * dx;
        dx = ca.y - ea.y; d2 += dx * dx;
        dx = ca.z - ea.z; d2 += dx * dx;
        dx = ca.w - ea.w; d2 += dx * dx;
        dx = cb.x - eb.x; d2 += dx * dx;
        dx = cb.y - eb.y; d2 += dx * dx;
        dx = cb.z - eb.z; d2 += dx * dx;
        dx = cb.w - eb.w; d2 += dx * dx;
#pragma unroll
        for (int off = 16; off; off >>= 1)
            d2 += __shfl_down_sync(0xffffffffu, d2, off);
        if (lane == 0 && d2 < best[TOPK_ - 1]) {
            int p = TOPK_ - 1;
            while (p > 0 && best[p - 1] > d2) {
                best[p] = best[p - 1]; bidx[p] = bidx[p - 1]; p--;
            }
            best[p] = d2; bidx[p] = row;
        }
    }

    if (lane == 0) {
#pragma unroll
        for (int i = 0; i < TOPK_; i++) { s_d2[warp][i] = best[i]; s_ix[warp][i] = bidx[i]; }
    }
    __syncthreads();

    if (tid == 0) {
        float fb[TOPK_]; int fi[TOPK_];
#pragma unroll
        for (int i = 0; i < TOPK_; i++) { fb[i] = 3.0e38f; fi[i] = -1; }
        for (int w = 0; w < 8; w++)
            for (int i = 0; i < TOPK_; i++) {
                float d2 = s_d2[w][i];
                if (d2 < fb[TOPK_ - 1]) {
                    int ix = s_ix[w][i];
                    int p = TOPK_ - 1;
                    while (p > 0 && fb[p - 1] > d2) {
                        fb[p] = fb[p - 1]; fi[p] = fi[p - 1]; p--;
                    }
                    fb[p] = d2; fi[p] = ix;
                }
            }
        int off = (b * DIST_BLOCKS + chunk) * TOPK_;
        for (int i = 0; i < TOPK_; i++) { g_cand_d2[off + i] = fb[i]; g_cand_idx[off + i] = fi[i]; }
        // publish + count
        __threadfence();
        unsigned int v = atomicAdd(&g_done[b], 1u);
        s_last = (v == DIST_BLOCKS - 1);
    }
    __syncthreads();

    if (!s_last) return;
    __threadfence();  // acquire: candidate writes from all blocks visible

    // ---- merge 1024 candidates for batch b (register keys + shfl) ----
    __shared__ unsigned long long warpmin[8];
    __shared__ unsigned long long winner;

    unsigned long long k[4];
    int base = b * NCAND;
#pragma unroll
    for (int s = 0; s < 4; s++) {
        int i = tid + s * 256;
        float d2 = g_cand_d2[base + i];
        int ix = g_cand_idx[base + i];
        k[s] = ((unsigned long long)__float_as_uint(d2) << 32) | (unsigned int)ix;
    }

    for (int sel = 0; sel < TOPK_; sel++) {
        unsigned long long m = u64min(u64min(k[0], k[1]), u64min(k[2], k[3]));
#pragma unroll
        for (int off = 16; off; off >>= 1)
            m = u64min(m, __shfl_down_sync(0xffffffffu, m, off));
        if (lane == 0) warpmin[warp] = m;
        __syncthreads();
        if (tid == 0) {
            unsigned long long w = warpmin[0];
#pragma unroll
            for (int i = 1; i < 8; i++) w = u64min(w, warpmin[i]);
            winner = w;
            g_topk_idx[b * TOPK_ + sel] = (int)(unsigned int)(w & 0xffffffffu);
        }
        __syncthreads();
        unsigned long long w = winner;
#pragma unroll
        for (int s = 0; s < 4; s++)
            if (k[s] == w) k[s] = ~0ULL;
        __syncthreads();
    }
    if (tid == 0) g_done[b] = 0;  // reset for next graph replay
}

// ---------------------------------------------------------------------------
// Kernel 3: fused gather + kv + kappa + vw. grid (4 slice, B), 512 thr.
// ---------------------------------------------------------------------------
__global__ void __launch_bounds__(512)
kw_kernel(const float* __restrict__ ctx,
          const float* __restrict__ Wk,
          const float* __restrict__ Wv,
          const float* __restrict__ Wout) {
    extern __shared__ float ksm[];
    float* rows = ksm;              // 8*512  (reps | labels)
    float* kv   = ksm + 4096;
    float* vv   = ksm + 8192;

    int slice = blockIdx.x, b = blockIdx.y;
    int tid = threadIdx.x;  // 512

#pragma unroll
    for (int j = 0; j < 8; j++) {
        int row = g_topk_idx[b * 8 + j];
        rows[j * 512 + tid] = ctx[((long)b * M_ + row) * D_ + tid];
    }
    __syncthreads();

    {
        float ak[8], av[8];
#pragma unroll
        for (int j = 0; j < 8; j++) { ak[j] = 0.f; av[j] = 0.f; }
#pragma unroll 4
        for (int r = 0; r < 256; r++) {
            float wk = Wk[r * 512 + tid];
            float wv = Wv[r * 512 + tid];
#pragma unroll
            for (int j = 0; j < 8; j++) {
                ak[j] += rows[j * 512 + 256 + r] * wk;
                av[j] += rows[j * 512 + r] * wv;
            }
        }
#pragma unroll
        for (int j = 0; j < 8; j++) {
            kv[j * 512 + tid] = ak[j];
            vv[j * 512 + tid] = av[j];
        }
    }
    __syncthreads();

    int hp = tid >> 7;
    int p  = slice * 128 + (tid & 127);

#pragma unroll
    for (int half = 0; half < 2; half++) {
        int h = hp + half * 4;
        {
            float aK[8];
#pragma unroll
            for (int j = 0; j < 8; j++) aK[j] = 0.f;
#pragma unroll 4
            for (int d = 0; d < 64; d++) {
                int i = h * 64 + d;
                float w = g_WqT[i * 512 + p];
#pragma unroll
                for (int j = 0; j < 8; j++) aK[j] += kv[j * 512 + i] * w;
            }
            long kbase = ((long)b * 512 + p) * 64 + h;
#pragma unroll
            for (int j = 0; j < 8; j++) g_kappa[kbase + j * 8] = aK[j] * SCALE_;
        }
        {
            float aV[8];
#pragma unroll
            for (int j = 0; j < 8; j++) aV[j] = 0.f;
#pragma unroll 4
            for (int d = 0; d < 64; d++) {
                int i = h * 64 + d;
                float w = Wout[i * 512 + p];
#pragma unroll
                for (int j = 0; j < 8; j++) aV[j] += vv[j * 512 + i] * w;
            }
#pragma unroll
            for (int j = 0; j < 8; j++)
                g_vw[((long)b * 64 + j * 8 + h) * 512 + p] = aV[j];
        }
    }
}

// ---------------------------------------------------------------------------
// Kernel 4: fused sim + softmax + out. f32x2 over COLUMN pairs (contiguous),
// round-7 row-major 68-stride tiling. grid (16, B), 256 thr, single wave.
// ---------------------------------------------------------------------------
#define STR 68

__global__ void __launch_bounds__(256)
fused_attn(const float* __restrict__ x,
           float* __restrict__ out,
           const float* __restrict__ bout) {
    extern __shared__ float fsm[];
    float* xs = fsm;          // 128*68: x chunk, then attention weights a
    float* ks = fsm + 128 * STR;  // 64*68: kappa chunk, then vw chunk

    int nc = blockIdx.x, b = blockIdx.y;
    int n0 = nc * 128;
    int tid = threadIdx.x;
    int ty = tid >> 4, tx = tid & 15;  // 8 tokens x (4 cols = 2 pairs)
    int tok0 = ty * 8;

    const float* xb = x + ((long)b * N_ + n0) * QD_;
    const float* kb = g_kappa + (long)b * QD_ * 64;

    unsigned long long acc2[8][2];
#pragma unroll
    for (int t = 0; t < 8; t++) { acc2[t][0] = 0ULL; acc2[t][1] = 0ULL; }

    // ---- phase 1: sim = x @ kappa, K in 8 chunks of 64 ----
    for (int pc = 0; pc < 8; pc++) {
        int p0 = pc * 64;
#pragma unroll
        for (int l = 0; l < 8; l++) {
            int f = tid + l * 256;
            int row = f >> 4, c4 = (f & 15) * 4;
            *(float4*)&xs[row * STR + c4] =
                *(const float4*)(xb + (long)row * QD_ + p0 + c4);
        }
#pragma unroll
        for (int l = 0; l < 4; l++) {
            int f = tid + l * 256;
            int row = f >> 4, c4 = (f & 15) * 4;
            *(float4*)&ks[row * STR + c4] =
                *(const float4*)(kb + (long)(p0 + row) * 64 + c4);
        }
        __syncthreads();

#pragma unroll
        for (int kk4 = 0; kk4 < 64; kk4 += 4) {
            float4 a4[8];
#pragma unroll
            for (int t = 0; t < 8; t++)
                a4[t] = *(const float4*)&xs[(tok0 + t) * STR + kk4];
#pragma unroll
            for (int q = 0; q < 4; q++) {
                ulonglong2 bp = *(const ulonglong2*)&ks[(kk4 + q) * STR + tx * 4];
#pragma unroll
                for (int t = 0; t < 8; t++) {
                    unsigned long long av = splat2(((const float*)&a4[t])[q]);
                    fma2(acc2[t][0], av, bp.x);
                    fma2(acc2[t][1], av, bp.y);
                }
            }
        }
        __syncthreads();
    }

    // ---- dump sim into xs[token][c] ----
#pragma unroll
    for (int t = 0; t < 8; t++) {
        float2 lo = unpack2(acc2[t][0]);
        float2 hi = unpack2(acc2[t][1]);
        *(float4*)&xs[(tok0 + t) * STR + tx * 4] =
            make_float4(lo.x, lo.y, hi.x, hi.y);
    }
    __syncthreads();

    // ---- softmax in place over j per (token, head) ----
#pragma unroll
    for (int s = 0; s < 4; s++) {
        int task = s * 256 + tid;
        int t = task >> 3, h = task & 7;
        float v[8];
#pragma unroll
        for (int j = 0; j < 8; j++) v[j] = xs[t * STR + j * 8 + h];
        float m = v[0];
#pragma unroll
        for (int j = 1; j < 8; j++) m = fmaxf(m, v[j]);
        float e[8], sum = 0.f;
#pragma unroll
        for (int j = 0; j < 8; j++) { e[j] = __expf(v[j] - m); sum += e[j]; }
        float inv = 1.f / sum;
#pragma unroll
        for (int j = 0; j < 8; j++) xs[t * STR + j * 8 + h] = e[j] * inv;
    }
    __syncthreads();

    // ---- phase 3: out = a @ vw + bias, 8 o-chunks of 64 ----
    const float* vwb = g_vw + (long)b * 64 * 512;
    float* ob = out + ((long)b * N_ + n0) * 512;

    for (int oc = 0; oc < 8; oc++) {
        int o0 = oc * 64;
#pragma unroll
        for (int l = 0; l < 4; l++) {
            int f = tid + l * 256;
            int row = f >> 4, c4 = (f & 15) * 4;
            *(float4*)&ks[row * STR + c4] =
                *(const float4*)(vwb + (long)row * 512 + o0 + c4);
        }
#pragma unroll
        for (int t = 0; t < 8; t++) { acc2[t][0] = 0ULL; acc2[t][1] = 0ULL; }
        __syncthreads();

#pragma unroll
        for (int cc4 = 0; cc4 < 64; cc4 += 4) {
            float4 a4[8];
#pragma unroll
            for (int t = 0; t < 8; t++)
                a4[t] = *(const float4*)&xs[(tok0 + t) * STR + cc4];
#pragma unroll
            for (int q = 0; q < 4; q++) {
                ulonglong2 bp = *(const ulonglong2*)&ks[(cc4 + q) * STR + tx * 4];
#pragma unroll
                for (int t = 0; t < 8; t++) {
                    unsigned long long av = splat2(((const float*)&a4[t])[q]);
                    fma2(acc2[t][0], av, bp.x);
                    fma2(acc2[t][1], av, bp.y);
                }
            }
        }

        float4 bias4 = *(const float4*)(bout + o0 + tx * 4);
#pragma unroll
        for (int t = 0; t < 8; t++) {
            float2 lo = unpack2(acc2[t][0]);
            float2 hi = unpack2(acc2[t][1]);
            float4 r = make_float4(lo.x + bias4.x, lo.y + bias4.y,
                                   hi.x + bias4.z, hi.y + bias4.w);
            *(float4*)(ob + (long)(tok0 + t) * 512 + o0 + tx * 4) = r;
        }
        __syncthreads();
    }
}

// ---------------------------------------------------------------------------
// Launch
// ---------------------------------------------------------------------------
extern "C" void kernel_launch(void* const* d_in, const int* in_sizes, int n_in,
                              void* d_out, int out_size) {
    const float* x    = (const float*)d_in[0];
    const float* ctx  = (const float*)d_in[1];
    const float* Wq   = (const float*)d_in[2];
    const float* Wk   = (const float*)d_in[3];
    const float* Wv   = (const float*)d_in[4];
    const float* We   = (const float*)d_in[5];
    const float* Wout = (const float*)d_in[6];
    const float* bout = (const float*)d_in[7];
    float* out = (float*)d_out;

    const int KW_SMEM = 3 * 4096 * sizeof(float);             // 48 KB
    const int FA_SMEM = (128 * STR + 64 * STR) * sizeof(float);  // ~51 KB
    cudaFuncSetAttribute(kw_kernel,
                         cudaFuncAttributeMaxDynamicSharedMemorySize, KW_SMEM);
    cudaFuncSetAttribute(fused_attn,
                         cudaFuncAttributeMaxDynamicSharedMemorySize, FA_SMEM);

    transpose512<<<dim3(16, 16), 256>>>(Wq);
    e0_kernel<<<B_, 512>>>(x, Wq, We);
    dist_topk_kernel<<<dim3(DIST_BLOCKS, B_), 256>>>(ctx);
    kw_kernel<<<dim3(4, B_), 512, KW_SMEM>>>(ctx, Wk, Wv, Wout);
    fused_attn<<<dim3(16, B_), 256, FA_SMEM>>>(x, out, bout);
}

// round 11
// speedup vs baseline: 1.3439x; 1.2912x over previous
#include <cuda_runtime.h>
#include <math.h>

// ---------------------------------------------------------------------------
// Problem constants
// ---------------------------------------------------------------------------
#define B_     8
#define N_     2048
#define M_     32768
#define QD_    512
#define DR_    256
#define D_     512
#define H_     8
#define DH_    64
#define INNER_ 512
#define TOPK_  8
#define SCALE_ 0.125f

#define DIST_BLOCKS 128
#define NCAND (DIST_BLOCKS * TOPK_)   // 1024

// ---------------------------------------------------------------------------
// Scratch
// ---------------------------------------------------------------------------
__device__ float g_e0[B_ * DR_];
__device__ float g_cand_d2[B_ * NCAND];
__device__ int   g_cand_idx[B_ * NCAND];
__device__ int   g_topk_idx[B_ * TOPK_];
__device__ float g_WqT[QD_ * INNER_];     // WqT[i][p] = Wq[p][i]
__device__ float g_kappa[B_ * QD_ * 64];  // [b][p][c], c=j*8+h (SCALE folded)
__device__ float g_vw[B_ * 64 * INNER_];  // [b][c][o]
__device__ unsigned int g_done[B_];       // zero-init; reset by last block

// ---------------------------------------------------------------------------
// f32x2 helpers
// ---------------------------------------------------------------------------
__device__ __forceinline__ unsigned long long splat2(float f) {
    unsigned long long r;
    asm("mov.b64 %0, {%1, %1};" : "=l"(r) : "f"(f));
    return r;
}
__device__ __forceinline__ void fma2(unsigned long long& d,
                                     unsigned long long a,
                                     unsigned long long b) {
    asm("fma.rn.f32x2 %0, %1, %2, %0;" : "+l"(d) : "l"(a), "l"(b));
}
__device__ __forceinline__ float2 unpack2(unsigned long long v) {
    float2 r;
    asm("mov.b64 {%0, %1}, %2;" : "=f"(r.x), "=f"(r.y) : "l"(v));
    return r;
}
__device__ __forceinline__ unsigned long long u64min(unsigned long long a,
                                                     unsigned long long b) {
    return a < b ? a : b;
}

// ---------------------------------------------------------------------------
// Kernel 0: transpose Wq -> g_WqT
// ---------------------------------------------------------------------------
__global__ void transpose512(const float* __restrict__ Wq) {
    __shared__ float tile[32][33];
    int bx = blockIdx.x * 32, by = blockIdx.y * 32;
    int tx = threadIdx.x & 31, ty = threadIdx.x >> 5;
#pragma unroll
    for (int r = ty; r < 32; r += 8)
        tile[r][tx] = Wq[(by + r) * 512 + bx + tx];
    __syncthreads();
#pragma unroll
    for (int r = ty; r < 32; r += 8)
        g_WqT[(bx + r) * 512 + by + tx] = tile[tx][r];
}

// ---------------------------------------------------------------------------
// Kernel 1: e0[b,:] = (x[b,0,:] @ Wq) @ We, split-K second stage
// ---------------------------------------------------------------------------
__global__ void e0_kernel(const float* __restrict__ x,
                          const float* __restrict__ Wq,
                          const float* __restrict__ We) {
    int b = blockIdx.x;
    int tid = threadIdx.x;  // 512
    __shared__ float xs[QD_];
    __shared__ float q0[QD_];
    __shared__ float part[512];

    xs[tid] = x[(long)b * N_ * QD_ + tid];
    __syncthreads();

    {
        float acc = 0.f;
#pragma unroll 16
        for (int c = 0; c < QD_; c++)
            acc += xs[c] * Wq[c * INNER_ + tid];
        q0[tid] = acc;
    }
    __syncthreads();

    {
        int half = tid >> 8;
        int o = tid & 255;
        int c0 = half * 256;
        float acc = 0.f;
#pragma unroll 16
        for (int c = 0; c < 256; c++)
            acc += q0[c0 + c] * We[(c0 + c) * DR_ + o];
        part[tid] = acc;
    }
    __syncthreads();
    if (tid < DR_)
        g_e0[b * DR_ + tid] = part[tid] + part[tid + 256];
}

// ---------------------------------------------------------------------------
// Kernel 2: distance scan + local top-8 + LAST-BLOCK global merge.
// grid (DIST_BLOCKS, B), 256 thr.
// ---------------------------------------------------------------------------
__global__ void dist_topk_kernel(const float* __restrict__ ctx) {
    int b = blockIdx.y;
    int chunk = blockIdx.x;
    int tid = threadIdx.x;
    int warp = tid >> 5, lane = tid & 31;

    __shared__ float es[DR_];
    __shared__ float s_d2[8][TOPK_];
    __shared__ int   s_ix[8][TOPK_];
    __shared__ int   s_last;

    if (tid < DR_) es[tid] = g_e0[b * DR_ + tid];
    __syncthreads();

    const float4* e4 = (const float4*)es;
    float4 ea = e4[lane];
    float4 eb = e4[lane + 32];

    float best[TOPK_];
    int   bidx[TOPK_];
#pragma unroll
    for (int i = 0; i < TOPK_; i++) { best[i] = 3.0e38f; bidx[i] = -1; }

    int row0 = chunk * 256 + warp * 32;
#pragma unroll 2
    for (int r = 0; r < 32; r++) {
        int row = row0 + r;
        const float4* crow = (const float4*)(ctx + ((long)b * M_ + row) * D_);
        float4 ca = crow[lane];
        float4 cb = crow[lane + 32];
        float dx, d2 = 0.f;
        dx = ca.x - ea.x; d2 += dx * dx;
        dx = ca.y - ea.y; d2 += dx * dx;
        dx = ca.z - ea.z; d2 += dx * dx;
        dx = ca.w - ea.w; d2 += dx * dx;
        dx = cb.x - eb.x; d2 += dx * dx;
        dx = cb.y - eb.y; d2 += dx * dx;
        dx = cb.z - eb.z; d2 += dx * dx;
        dx = cb.w - eb.w; d2 += dx * dx;
#pragma unroll
        for (int off = 16; off; off >>= 1)
            d2 += __shfl_down_sync(0xffffffffu, d2, off);
        if (lane == 0 && d2 < best[TOPK_ - 1]) {
            int p = TOPK_ - 1;
            while (p > 0 && best[p - 1] > d2) {
                best[p] = best[p - 1]; bidx[p] = bidx[p - 1]; p--;
            }
            best[p] = d2; bidx[p] = row;
        }
    }

    if (lane == 0) {
#pragma unroll
        for (int i = 0; i < TOPK_; i++) { s_d2[warp][i] = best[i]; s_ix[warp][i] = bidx[i]; }
    }
    __syncthreads();

    if (tid == 0) {
        float fb[TOPK_]; int fi[TOPK_];
#pragma unroll
        for (int i = 0; i < TOPK_; i++) { fb[i] = 3.0e38f; fi[i] = -1; }
        for (int w = 0; w < 8; w++)
            for (int i = 0; i < TOPK_; i++) {
                float d2 = s_d2[w][i];
                if (d2 < fb[TOPK_ - 1]) {
                    int ix = s_ix[w][i];
                    int p = TOPK_ - 1;
                    while (p > 0 && fb[p - 1] > d2) {
                        fb[p] = fb[p - 1]; fi[p] = fi[p - 1]; p--;
                    }
                    fb[p] = d2; fi[p] = ix;
                }
            }
        int off = (b * DIST_BLOCKS + chunk) * TOPK_;
        for (int i = 0; i < TOPK_; i++) { g_cand_d2[off + i] = fb[i]; g_cand_idx[off + i] = fi[i]; }
        __threadfence();
        unsigned int v = atomicAdd(&g_done[b], 1u);
        s_last = (v == DIST_BLOCKS - 1);
    }
    __syncthreads();

    if (!s_last) return;
    __threadfence();  // acquire

    // ---- merge 1024 candidates (register keys + shfl) ----
    __shared__ unsigned long long warpmin[8];
    __shared__ unsigned long long winner;

    unsigned long long k[4];
    int base = b * NCAND;
#pragma unroll
    for (int s = 0; s < 4; s++) {
        int i = tid + s * 256;
        float d2 = g_cand_d2[base + i];
        int ix = g_cand_idx[base + i];
        k[s] = ((unsigned long long)__float_as_uint(d2) << 32) | (unsigned int)ix;
    }

    for (int sel = 0; sel < TOPK_; sel++) {
        unsigned long long m = u64min(u64min(k[0], k[1]), u64min(k[2], k[3]));
#pragma unroll
        for (int off = 16; off; off >>= 1)
            m = u64min(m, __shfl_down_sync(0xffffffffu, m, off));
        if (lane == 0) warpmin[warp] = m;
        __syncthreads();
        if (tid == 0) {
            unsigned long long w = warpmin[0];
#pragma unroll
            for (int i = 1; i < 8; i++) w = u64min(w, warpmin[i]);
            winner = w;
            g_topk_idx[b * TOPK_ + sel] = (int)(unsigned int)(w & 0xffffffffu);
        }
        __syncthreads();
        unsigned long long w = winner;
#pragma unroll
        for (int s = 0; s < 4; s++)
            if (k[s] == w) k[s] = ~0ULL;
        __syncthreads();
    }
    if (tid == 0) g_done[b] = 0;  // reset for graph replay
}

// ---------------------------------------------------------------------------
// Kernel 3: fused kv + kappa + vw. grid (64 bj, 4 slice), 512 thr.
// (round-7 high-parallelism version: 256 blocks, redundant cheap k/v per block)
// ---------------------------------------------------------------------------
__global__ void __launch_bounds__(512)
kvkv_kernel(const float* __restrict__ ctx,
            const float* __restrict__ Wk,
            const float* __restrict__ Wv,
            const float* __restrict__ Wout) {
    int bj = blockIdx.x;
    int slice = blockIdx.y;
    int b = bj >> 3, j = bj & 7;
    int tid = threadIdx.x;  // 512

    __shared__ float labels[DR_];
    __shared__ float reps[DR_];
    __shared__ float kvec[INNER_];
    __shared__ float vvec[INNER_];

    int row = g_topk_idx[bj];
    const float* crow = ctx + ((long)b * M_ + row) * D_;
    if (tid < 256) reps[tid] = crow[tid];
    else           labels[tid - 256] = crow[tid];
    __syncthreads();

    {
        float ak = 0.f, av = 0.f;
#pragma unroll 8
        for (int r = 0; r < DR_; r++) {
            float l = labels[r], rr = reps[r];
            ak += l * Wk[r * INNER_ + tid];
            av += rr * Wv[r * INNER_ + tid];
        }
        kvec[tid] = ak;
        vvec[tid] = av;
    }
    __syncthreads();

    int hp = tid >> 7;           // 0..3 -> heads hp and hp+4
    int pl = tid & 127;
    int p = slice * 128 + pl;

    // kappa
    {
        float aK0 = 0.f, aK1 = 0.f;
#pragma unroll 8
        for (int d = 0; d < 64; d++) {
            int i0 = hp * 64 + d;
            int i1 = (hp + 4) * 64 + d;
            aK0 += g_WqT[i0 * 512 + p] * kvec[i0];
            aK1 += g_WqT[i1 * 512 + p] * kvec[i1];
        }
        long kb = ((long)b * 512 + p) * 64 + j * 8;
        g_kappa[kb + hp]     = aK0 * SCALE_;
        g_kappa[kb + hp + 4] = aK1 * SCALE_;
    }

    // vw
    {
        float aV0 = 0.f, aV1 = 0.f;
#pragma unroll 8
        for (int d = 0; d < 64; d++) {
            int i0 = hp * 64 + d;
            int i1 = (hp + 4) * 64 + d;
            aV0 += Wout[i0 * 512 + p] * vvec[i0];
            aV1 += Wout[i1 * 512 + p] * vvec[i1];
        }
        g_vw[((long)b * 64 + j * 8 + hp) * 512 + p]     = aV0;
        g_vw[((long)b * 64 + j * 8 + hp + 4) * 512 + p] = aV1;
    }
}

// ---------------------------------------------------------------------------
// Kernel 4: fused sim + softmax + out. f32x2 over COLUMN pairs (contiguous),
// row-major 68-stride tiling. grid (16, B), 256 thr, single wave.
// ---------------------------------------------------------------------------
#define STR 68

__global__ void __launch_bounds__(256)
fused_attn(const float* __restrict__ x,
           float* __restrict__ out,
           const float* __restrict__ bout) {
    extern __shared__ float fsm[];
    float* xs = fsm;              // 128*68: x chunk, then attention weights a
    float* ks = fsm + 128 * STR;  // 64*68: kappa chunk, then vw chunk

    int nc = blockIdx.x, b = blockIdx.y;
    int n0 = nc * 128;
    int tid = threadIdx.x;
    int ty = tid >> 4, tx = tid & 15;  // 8 tokens x (4 cols = 2 pairs)
    int tok0 = ty * 8;

    const float* xb = x + ((long)b * N_ + n0) * QD_;
    const float* kb = g_kappa + (long)b * QD_ * 64;

    unsigned long long acc2[8][2];
#pragma unroll
    for (int t = 0; t < 8; t++) { acc2[t][0] = 0ULL; acc2[t][1] = 0ULL; }

    // ---- phase 1: sim = x @ kappa, K in 8 chunks of 64 ----
    for (int pc = 0; pc < 8; pc++) {
        int p0 = pc * 64;
#pragma unroll
        for (int l = 0; l < 8; l++) {
            int f = tid + l * 256;
            int row = f >> 4, c4 = (f & 15) * 4;
            *(float4*)&xs[row * STR + c4] =
                *(const float4*)(xb + (long)row * QD_ + p0 + c4);
        }
#pragma unroll
        for (int l = 0; l < 4; l++) {
            int f = tid + l * 256;
            int row = f >> 4, c4 = (f & 15) * 4;
            *(float4*)&ks[row * STR + c4] =
                *(const float4*)(kb + (long)(p0 + row) * 64 + c4);
        }
        __syncthreads();

#pragma unroll
        for (int kk4 = 0; kk4 < 64; kk4 += 4) {
            float4 a4[8];
#pragma unroll
            for (int t = 0; t < 8; t++)
                a4[t] = *(const float4*)&xs[(tok0 + t) * STR + kk4];
#pragma unroll
            for (int q = 0; q < 4; q++) {
                ulonglong2 bp = *(const ulonglong2*)&ks[(kk4 + q) * STR + tx * 4];
#pragma unroll
                for (int t = 0; t < 8; t++) {
                    unsigned long long av = splat2(((const float*)&a4[t])[q]);
                    fma2(acc2[t][0], av, bp.x);
                    fma2(acc2[t][1], av, bp.y);
                }
            }
        }
        __syncthreads();
    }

    // ---- dump sim into xs[token][c] ----
#pragma unroll
    for (int t = 0; t < 8; t++) {
        float2 lo = unpack2(acc2[t][0]);
        float2 hi = unpack2(acc2[t][1]);
        *(float4*)&xs[(tok0 + t) * STR + tx * 4] =
            make_float4(lo.x, lo.y, hi.x, hi.y);
    }
    __syncthreads();

    // ---- softmax in place over j per (token, head) ----
#pragma unroll
    for (int s = 0; s < 4; s++) {
        int task = s * 256 + tid;
        int t = task >> 3, h = task & 7;
        float v[8];
#pragma unroll
        for (int j = 0; j < 8; j++) v[j] = xs[t * STR + j * 8 + h];
        float m = v[0];
#pragma unroll
        for (int j = 1; j < 8; j++) m = fmaxf(m, v[j]);
        float e[8], sum = 0.f;
#pragma unroll
        for (int j = 0; j < 8; j++) { e[j] = __expf(v[j] - m); sum += e[j]; }
        float inv = 1.f / sum;
#pragma unroll
        for (int j = 0; j < 8; j++) xs[t * STR + j * 8 + h] = e[j] * inv;
    }
    __syncthreads();

    // ---- phase 3: out = a @ vw + bias, 8 o-chunks of 64 ----
    const float* vwb = g_vw + (long)b * 64 * 512;
    float* ob = out + ((long)b * N_ + n0) * 512;

    for (int oc = 0; oc < 8; oc++) {
        int o0 = oc * 64;
#pragma unroll
        for (int l = 0; l < 4; l++) {
            int f = tid + l * 256;
            int row = f >> 4, c4 = (f & 15) * 4;
            *(float4*)&ks[row * STR + c4] =
                *(const float4*)(vwb + (long)row * 512 + o0 + c4);
        }
#pragma unroll
        for (int t = 0; t < 8; t++) { acc2[t][0] = 0ULL; acc2[t][1] = 0ULL; }
        __syncthreads();

#pragma unroll
        for (int cc4 = 0; cc4 < 64; cc4 += 4) {
            float4 a4[8];
#pragma unroll
            for (int t = 0; t < 8; t++)
                a4[t] = *(const float4*)&xs[(tok0 + t) * STR + cc4];
#pragma unroll
            for (int q = 0; q < 4; q++) {
                ulonglong2 bp = *(const ulonglong2*)&ks[(cc4 + q) * STR + tx * 4];
#pragma unroll
                for (int t = 0; t < 8; t++) {
                    unsigned long long av = splat2(((const float*)&a4[t])[q]);
                    fma2(acc2[t][0], av, bp.x);
                    fma2(acc2[t][1], av, bp.y);
                }
            }
        }

        float4 bias4 = *(const float4*)(bout + o0 + tx * 4);
#pragma unroll
        for (int t = 0; t < 8; t++) {
            float2 lo = unpack2(acc2[t][0]);
            float2 hi = unpack2(acc2[t][1]);
            float4 r = make_float4(lo.x + bias4.x, lo.y + bias4.y,
                                   hi.x + bias4.z, hi.y + bias4.w);
            *(float4*)(ob + (long)(tok0 + t) * 512 + o0 + tx * 4) = r;
        }
        __syncthreads();
    }
}

// ---------------------------------------------------------------------------
// Launch
// ---------------------------------------------------------------------------
extern "C" void kernel_launch(void* const* d_in, const int* in_sizes, int n_in,
                              void* d_out, int out_size) {
    const float* x    = (const float*)d_in[0];
    const float* ctx  = (const float*)d_in[1];
    const float* Wq   = (const float*)d_in[2];
    const float* Wk   = (const float*)d_in[3];
    const float* Wv   = (const float*)d_in[4];
    const float* We   = (const float*)d_in[5];
    const float* Wout = (const float*)d_in[6];
    const float* bout = (const float*)d_in[7];
    float* out = (float*)d_out;

    const int FA_SMEM = (128 * STR + 64 * STR) * sizeof(float);  // ~51 KB
    cudaFuncSetAttribute(fused_attn,
                         cudaFuncAttributeMaxDynamicSharedMemorySize, FA_SMEM);

    transpose512<<<dim3(16, 16), 256>>>(Wq);
    e0_kernel<<<B_, 512>>>(x, Wq, We);
    dist_topk_kernel<<<dim3(DIST_BLOCKS, B_), 256>>>(ctx);
    kvkv_kernel<<<dim3(64, 4), 512>>>(ctx, Wk, Wv, Wout);
    fused_attn<<<dim3(16, B_), 256, FA_SMEM>>>(x, out, bout);
}

// round 12
// speedup vs baseline: 1.5283x; 1.1372x over previous
#include <cuda_runtime.h>
#include <math.h>

// ---------------------------------------------------------------------------
// Problem constants
// ---------------------------------------------------------------------------
#define B_     8
#define N_     2048
#define M_     32768
#define QD_    512
#define DR_    256
#define D_     512
#define H_     8
#define DH_    64
#define INNER_ 512
#define TOPK_  8
#define SCALE_ 0.125f

#define DIST_BLOCKS 128
#define NCAND (DIST_BLOCKS * TOPK_)   // 1024

// ---------------------------------------------------------------------------
// Scratch
// ---------------------------------------------------------------------------
__device__ float g_e0[B_ * DR_];
__device__ float g_cand_d2[B_ * NCAND];
__device__ int   g_cand_idx[B_ * NCAND];
__device__ int   g_topk_idx[B_ * TOPK_];
__device__ float g_WqT[QD_ * INNER_];     // WqT[i][p] = Wq[p][i]
__device__ float g_khat[B_ * 64 * 64];    // [b][c=j*8+h][d] = k[b][j][h*64+d]
__device__ float g_vhat[B_ * 64 * 64];    // [b][c][d]       = v[b][j][h*64+d]
__device__ float g_kappa[B_ * QD_ * 64];  // [b][p][c], c=j*8+h (SCALE folded)
__device__ float g_vw[B_ * 64 * INNER_];  // [b][c][o]
__device__ unsigned int g_done[B_];       // zero-init; reset by last block

// ---------------------------------------------------------------------------
// f32x2 helpers
// ---------------------------------------------------------------------------
__device__ __forceinline__ unsigned long long splat2(float f) {
    unsigned long long r;
    asm("mov.b64 %0, {%1, %1};" : "=l"(r) : "f"(f));
    return r;
}
__device__ __forceinline__ void fma2(unsigned long long& d,
                                     unsigned long long a,
                                     unsigned long long b) {
    asm("fma.rn.f32x2 %0, %1, %2, %0;" : "+l"(d) : "l"(a), "l"(b));
}
__device__ __forceinline__ float2 unpack2(unsigned long long v) {
    float2 r;
    asm("mov.b64 {%0, %1}, %2;" : "=f"(r.x), "=f"(r.y) : "l"(v));
    return r;
}
__device__ __forceinline__ unsigned long long u64min(unsigned long long a,
                                                     unsigned long long b) {
    return a < b ? a : b;
}

// ---------------------------------------------------------------------------
// Kernel 0: transpose Wq -> g_WqT
// ---------------------------------------------------------------------------
__global__ void transpose512(const float* __restrict__ Wq) {
    __shared__ float tile[32][33];
    int bx = blockIdx.x * 32, by = blockIdx.y * 32;
    int tx = threadIdx.x & 31, ty = threadIdx.x >> 5;
#pragma unroll
    for (int r = ty; r < 32; r += 8)
        tile[r][tx] = Wq[(by + r) * 512 + bx + tx];
    __syncthreads();
#pragma unroll
    for (int r = ty; r < 32; r += 8)
        g_WqT[(bx + r) * 512 + by + tx] = tile[tx][r];
}

// ---------------------------------------------------------------------------
// Kernel 1: e0[b,:] = (x[b,0,:] @ Wq) @ We, split-K second stage
// ---------------------------------------------------------------------------
__global__ void e0_kernel(const float* __restrict__ x,
                          const float* __restrict__ Wq,
                          const float* __restrict__ We) {
    int b = blockIdx.x;
    int tid = threadIdx.x;  // 512
    __shared__ float xs[QD_];
    __shared__ float q0[QD_];
    __shared__ float part[512];

    xs[tid] = x[(long)b * N_ * QD_ + tid];
    __syncthreads();

    {
        float acc = 0.f;
#pragma unroll 16
        for (int c = 0; c < QD_; c++)
            acc += xs[c] * Wq[c * INNER_ + tid];
        q0[tid] = acc;
    }
    __syncthreads();

    {
        int half = tid >> 8;
        int o = tid & 255;
        int c0 = half * 256;
        float acc = 0.f;
#pragma unroll 16
        for (int c = 0; c < 256; c++)
            acc += q0[c0 + c] * We[(c0 + c) * DR_ + o];
        part[tid] = acc;
    }
    __syncthreads();
    if (tid < DR_)
        g_e0[b * DR_ + tid] = part[tid] + part[tid + 256];
}

// ---------------------------------------------------------------------------
// Kernel 2: distance scan + local top-8 + LAST-BLOCK global merge.
// grid (DIST_BLOCKS, B), 256 thr.
// ---------------------------------------------------------------------------
__global__ void dist_topk_kernel(const float* __restrict__ ctx) {
    int b = blockIdx.y;
    int chunk = blockIdx.x;
    int tid = threadIdx.x;
    int warp = tid >> 5, lane = tid & 31;

    __shared__ float es[DR_];
    __shared__ float s_d2[8][TOPK_];
    __shared__ int   s_ix[8][TOPK_];
    __shared__ int   s_last;

    if (tid < DR_) es[tid] = g_e0[b * DR_ + tid];
    __syncthreads();

    const float4* e4 = (const float4*)es;
    float4 ea = e4[lane];
    float4 eb = e4[lane + 32];

    float best[TOPK_];
    int   bidx[TOPK_];
#pragma unroll
    for (int i = 0; i < TOPK_; i++) { best[i] = 3.0e38f; bidx[i] = -1; }

    int row0 = chunk * 256 + warp * 32;
#pragma unroll 2
    for (int r = 0; r < 32; r++) {
        int row = row0 + r;
        const float4* crow = (const float4*)(ctx + ((long)b * M_ + row) * D_);
        float4 ca = crow[lane];
        float4 cb = crow[lane + 32];
        float dx, d2 = 0.f;
        dx = ca.x - ea.x; d2 += dx * dx;
        dx = ca.y - ea.y; d2 += dx * dx;
        dx = ca.z - ea.z; d2 += dx * dx;
        dx = ca.w - ea.w; d2 += dx * dx;
        dx = cb.x - eb.x; d2 += dx * dx;
        dx = cb.y - eb.y; d2 += dx * dx;
        dx = cb.z - eb.z; d2 += dx * dx;
        dx = cb.w - eb.w; d2 += dx * dx;
#pragma unroll
        for (int off = 16; off; off >>= 1)
            d2 += __shfl_down_sync(0xffffffffu, d2, off);
        if (lane == 0 && d2 < best[TOPK_ - 1]) {
            int p = TOPK_ - 1;
            while (p > 0 && best[p - 1] > d2) {
                best[p] = best[p - 1]; bidx[p] = bidx[p - 1]; p--;
            }
            best[p] = d2; bidx[p] = row;
        }
    }

    if (lane == 0) {
#pragma unroll
        for (int i = 0; i < TOPK_; i++) { s_d2[warp][i] = best[i]; s_ix[warp][i] = bidx[i]; }
    }
    __syncthreads();

    if (tid == 0) {
        float fb[TOPK_]; int fi[TOPK_];
#pragma unroll
        for (int i = 0; i < TOPK_; i++) { fb[i] = 3.0e38f; fi[i] = -1; }
        for (int w = 0; w < 8; w++)
            for (int i = 0; i < TOPK_; i++) {
                float d2 = s_d2[w][i];
                if (d2 < fb[TOPK_ - 1]) {
                    int ix = s_ix[w][i];
                    int p = TOPK_ - 1;
                    while (p > 0 && fb[p - 1] > d2) {
                        fb[p] = fb[p - 1]; fi[p] = fi[p - 1]; p--;
                    }
                    fb[p] = d2; fi[p] = ix;
                }
            }
        int off = (b * DIST_BLOCKS + chunk) * TOPK_;
        for (int i = 0; i < TOPK_; i++) { g_cand_d2[off + i] = fb[i]; g_cand_idx[off + i] = fi[i]; }
        __threadfence();
        unsigned int v = atomicAdd(&g_done[b], 1u);
        s_last = (v == DIST_BLOCKS - 1);
    }
    __syncthreads();

    if (!s_last) return;
    __threadfence();  // acquire

    // ---- merge 1024 candidates (register keys + shfl) ----
    __shared__ unsigned long long warpmin[8];
    __shared__ unsigned long long winner;

    unsigned long long k[4];
    int base = b * NCAND;
#pragma unroll
    for (int s = 0; s < 4; s++) {
        int i = tid + s * 256;
        float d2 = g_cand_d2[base + i];
        int ix = g_cand_idx[base + i];
        k[s] = ((unsigned long long)__float_as_uint(d2) << 32) | (unsigned int)ix;
    }

    for (int sel = 0; sel < TOPK_; sel++) {
        unsigned long long m = u64min(u64min(k[0], k[1]), u64min(k[2], k[3]));
#pragma unroll
        for (int off = 16; off; off >>= 1)
            m = u64min(m, __shfl_down_sync(0xffffffffu, m, off));
        if (lane == 0) warpmin[warp] = m;
        __syncthreads();
        if (tid == 0) {
            unsigned long long w = warpmin[0];
#pragma unroll
            for (int i = 1; i < 8; i++) w = u64min(w, warpmin[i]);
            winner = w;
            g_topk_idx[b * TOPK_ + sel] = (int)(unsigned int)(w & 0xffffffffu);
        }
        __syncthreads();
        unsigned long long w = winner;
#pragma unroll
        for (int s = 0; s < 4; s++)
            if (k[s] == w) k[s] = ~0ULL;
        __syncthreads();
    }
    if (tid == 0) g_done[b] = 0;  // reset for graph replay
}

// ---------------------------------------------------------------------------
// Kernel 3a: k/v vectors. grid (64 bj), 1024 thr.
// Threads 0-511: k column; 512-1023: v column. Each weight matrix read once
// per bj. Output reindexed by head: khat[b][c=j*8+h][d], vhat likewise.
// ---------------------------------------------------------------------------
__global__ void __launch_bounds__(1024)
kvA_kernel(const float* __restrict__ ctx,
           const float* __restrict__ Wk,
           const float* __restrict__ Wv) {
    int bj = blockIdx.x;
    int b = bj >> 3, j = bj & 7;
    int tid = threadIdx.x;  // 1024

    __shared__ float reps[DR_];
    __shared__ float labels[DR_];

    int row = g_topk_idx[bj];
    const float* crow = ctx + ((long)b * M_ + row) * D_;
    if (tid < 256)      reps[tid] = crow[tid];
    else if (tid < 512) labels[tid - 256] = crow[tid];
    __syncthreads();

    int col = tid & 511;
    bool isK = tid < 512;
    const float* W   = isK ? Wk : Wv;
    const float* vec = isK ? labels : reps;

    float acc = 0.f;
#pragma unroll 16
    for (int r = 0; r < DR_; r++)
        acc += vec[r] * W[r * INNER_ + col];

    int h = col >> 6, d = col & 63;
    long dst = ((long)b * 64 + j * 8 + h) * 64 + d;
    if (isK) g_khat[dst] = acc;
    else     g_vhat[dst] = acc;
}

// ---------------------------------------------------------------------------
// Kernel 3b: kappa + vw from khat/vhat. grid (8 h, 8 b), 512 thr.
// All 8 j share every WqT/Wout read; khat/vhat slices live in smem.
//   kappa[b][p][j*8+h] = SCALE * sum_d WqT[h*64+d][p] * khat[b][j*8+h][d]
//   vw[b][j*8+h][o]    =         sum_d vhat[b][j*8+h][d] * Wout[h*64+d][o]
// ---------------------------------------------------------------------------
__global__ void __launch_bounds__(512)
kwB_kernel(const float* __restrict__ Wout) {
    int h = blockIdx.x, b = blockIdx.y;
    int tid = threadIdx.x;  // 512 -> p (kappa) / o (vw)

    __shared__ float kh[8][64];
    __shared__ float vh[8][64];
    {
        int j = tid >> 6, d = tid & 63;
        long src = ((long)b * 64 + j * 8 + h) * 64 + d;
        kh[j][d] = g_khat[src];
        vh[j][d] = g_vhat[src];
    }
    __syncthreads();

    // kappa: thread = p
    {
        float acc[8];
#pragma unroll
        for (int j = 0; j < 8; j++) acc[j] = 0.f;
#pragma unroll 8
        for (int d = 0; d < 64; d++) {
            float w = g_WqT[(h * 64 + d) * 512 + tid];
#pragma unroll
            for (int j = 0; j < 8; j++) acc[j] += w * kh[j][d];
        }
        long kbase = ((long)b * 512 + tid) * 64 + h;
#pragma unroll
        for (int j = 0; j < 8; j++) g_kappa[kbase + j * 8] = acc[j] * SCALE_;
    }

    // vw: thread = o
    {
        float acc[8];
#pragma unroll
        for (int j = 0; j < 8; j++) acc[j] = 0.f;
#pragma unroll 8
        for (int d = 0; d < 64; d++) {
            float w = Wout[(h * 64 + d) * 512 + tid];
#pragma unroll
            for (int j = 0; j < 8; j++) acc[j] += vh[j][d] * w;
        }
#pragma unroll
        for (int j = 0; j < 8; j++)
            g_vw[((long)b * 64 + j * 8 + h) * 512 + tid] = acc[j];
    }
}

// ---------------------------------------------------------------------------
// Kernel 4: fused sim + softmax + out. f32x2 over COLUMN pairs (contiguous),
// row-major 68-stride tiling. grid (16, B), 256 thr, single wave.
// ---------------------------------------------------------------------------
#define STR 68

__global__ void __launch_bounds__(256)
fused_attn(const float* __restrict__ x,
           float* __restrict__ out,
           const float* __restrict__ bout) {
    extern __shared__ float fsm[];
    float* xs = fsm;              // 128*68: x chunk, then attention weights a
    float* ks = fsm + 128 * STR;  // 64*68: kappa chunk, then vw chunk

    int nc = blockIdx.x, b = blockIdx.y;
    int n0 = nc * 128;
    int tid = threadIdx.x;
    int ty = tid >> 4, tx = tid & 15;  // 8 tokens x (4 cols = 2 pairs)
    int tok0 = ty * 8;

    const float* xb = x + ((long)b * N_ + n0) * QD_;
    const float* kb = g_kappa + (long)b * QD_ * 64;

    unsigned long long acc2[8][2];
#pragma unroll
    for (int t = 0; t < 8; t++) { acc2[t][0] = 0ULL; acc2[t][1] = 0ULL; }

    // ---- phase 1: sim = x @ kappa, K in 8 chunks of 64 ----
    for (int pc = 0; pc < 8; pc++) {
        int p0 = pc * 64;
#pragma unroll
        for (int l = 0; l < 8; l++) {
            int f = tid + l * 256;
            int row = f >> 4, c4 = (f & 15) * 4;
            *(float4*)&xs[row * STR + c4] =
                *(const float4*)(xb + (long)row * QD_ + p0 + c4);
        }
#pragma unroll
        for (int l = 0; l < 4; l++) {
            int f = tid + l * 256;
            int row = f >> 4, c4 = (f & 15) * 4;
            *(float4*)&ks[row * STR + c4] =
                *(const float4*)(kb + (long)(p0 + row) * 64 + c4);
        }
        __syncthreads();

#pragma unroll
        for (int kk4 = 0; kk4 < 64; kk4 += 4) {
            float4 a4[8];
#pragma unroll
            for (int t = 0; t < 8; t++)
                a4[t] = *(const float4*)&xs[(tok0 + t) * STR + kk4];
#pragma unroll
            for (int q = 0; q < 4; q++) {
                ulonglong2 bp = *(const ulonglong2*)&ks[(kk4 + q) * STR + tx * 4];
#pragma unroll
                for (int t = 0; t < 8; t++) {
                    unsigned long long av = splat2(((const float*)&a4[t])[q]);
                    fma2(acc2[t][0], av, bp.x);
                    fma2(acc2[t][1], av, bp.y);
                }
            }
        }
        __syncthreads();
    }

    // ---- dump sim into xs[token][c] ----
#pragma unroll
    for (int t = 0; t < 8; t++) {
        float2 lo = unpack2(acc2[t][0]);
        float2 hi = unpack2(acc2[t][1]);
        *(float4*)&xs[(tok0 + t) * STR + tx * 4] =
            make_float4(lo.x, lo.y, hi.x, hi.y);
    }
    __syncthreads();

    // ---- softmax in place over j per (token, head) ----
#pragma unroll
    for (int s = 0; s < 4; s++) {
        int task = s * 256 + tid;
        int t = task >> 3, h = task & 7;
        float v[8];
#pragma unroll
        for (int j = 0; j < 8; j++) v[j] = xs[t * STR + j * 8 + h];
        float m = v[0];
#pragma unroll
        for (int j = 1; j < 8; j++) m = fmaxf(m, v[j]);
        float e[8], sum = 0.f;
#pragma unroll
        for (int j = 0; j < 8; j++) { e[j] = __expf(v[j] - m); sum += e[j]; }
        float inv = 1.f / sum;
#pragma unroll
        for (int j = 0; j < 8; j++) xs[t * STR + j * 8 + h] = e[j] * inv;
    }
    __syncthreads();

    // ---- phase 3: out = a @ vw + bias, 8 o-chunks of 64 ----
    const float* vwb = g_vw + (long)b * 64 * 512;
    float* ob = out + ((long)b * N_ + n0) * 512;

    for (int oc = 0; oc < 8; oc++) {
        int o0 = oc * 64;
#pragma unroll
        for (int l = 0; l < 4; l++) {
            int f = tid + l * 256;
            int row = f >> 4, c4 = (f & 15) * 4;
            *(float4*)&ks[row * STR + c4] =
                *(const float4*)(vwb + (long)row * 512 + o0 + c4);
        }
#pragma unroll
        for (int t = 0; t < 8; t++) { acc2[t][0] = 0ULL; acc2[t][1] = 0ULL; }
        __syncthreads();

#pragma unroll
        for (int cc4 = 0; cc4 < 64; cc4 += 4) {
            float4 a4[8];
#pragma unroll
            for (int t = 0; t < 8; t++)
                a4[t] = *(const float4*)&xs[(tok0 + t) * STR + cc4];
#pragma unroll
            for (int q = 0; q < 4; q++) {
                ulonglong2 bp = *(const ulonglong2*)&ks[(cc4 + q) * STR + tx * 4];
#pragma unroll
                for (int t = 0; t < 8; t++) {
                    unsigned long long av = splat2(((const float*)&a4[t])[q]);
                    fma2(acc2[t][0], av, bp.x);
                    fma2(acc2[t][1], av, bp.y);
                }
            }
        }

        float4 bias4 = *(const float4*)(bout + o0 + tx * 4);
#pragma unroll
        for (int t = 0; t < 8; t++) {
            float2 lo = unpack2(acc2[t][0]);
            float2 hi = unpack2(acc2[t][1]);
            float4 r = make_float4(lo.x + bias4.x, lo.y + bias4.y,
                                   hi.x + bias4.z, hi.y + bias4.w);
            *(float4*)(ob + (long)(tok0 + t) * 512 + o0 + tx * 4) = r;
        }
        __syncthreads();
    }
}

// ---------------------------------------------------------------------------
// Launch
// ---------------------------------------------------------------------------
extern "C" void kernel_launch(void* const* d_in, const int* in_sizes, int n_in,
                              void* d_out, int out_size) {
    const float* x    = (const float*)d_in[0];
    const float* ctx  = (const float*)d_in[1];
    const float* Wq   = (const float*)d_in[2];
    const float* Wk   = (const float*)d_in[3];
    const float* Wv   = (const float*)d_in[4];
    const float* We   = (const float*)d_in[5];
    const float* Wout = (const float*)d_in[6];
    const float* bout = (const float*)d_in[7];
    float* out = (float*)d_out;

    const int FA_SMEM = (128 * STR + 64 * STR) * sizeof(float);  // ~51 KB
    cudaFuncSetAttribute(fused_attn,
                         cudaFuncAttributeMaxDynamicSharedMemorySize, FA_SMEM);

    transpose512<<<dim3(16, 16), 256>>>(Wq);
    e0_kernel<<<B_, 512>>>(x, Wq, We);
    dist_topk_kernel<<<dim3(DIST_BLOCKS, B_), 256>>>(ctx);
    kvA_kernel<<<64, 1024>>>(ctx, Wk, Wv);
    kwB_kernel<<<dim3(8, 8), 512>>>(Wout);
    fused_attn<<<dim3(16, B_), 256, FA_SMEM>>>(x, out, bout);
}